// round 3
// baseline (speedup 1.0000x reference)
#include <cuda_runtime.h>
#include <cuda_bf16.h>

// ---------------- problem constants ----------------
#define BATCH   64
#define T_IN    8192
#define T2      4096        // after pool1
#define T4      2048        // after pool2
#define N_NODES 131072      // BATCH * T4
#define N_EDGES 2097152
#define HID     64
#define OUTC    10

// ---------------- scratch (device globals, no allocation) ----------------
// NOTE: these symbols are referenced ONLY inside device code. Passing them as
// kernel arguments from host code silently passes the host shadow address,
// which GB300's ATS happily dereferences (reads zeros) without faulting.
__device__ float g_h1[BATCH * 16 * T2];          // conv1 output pooled [b][c][t]
__device__ float g_feat[N_NODES * 32];           // conv2 output, node-major
__device__ float g_y[N_NODES * 64];              // dis * (f @ W)  (reused both layers)
__device__ float g_g1[N_NODES * 64];             // gcn1 output
__device__ float g_g2[N_NODES * 64];             // gcn2 output
__device__ float g_dis[N_NODES];
__device__ int   g_cnt[N_NODES];
__device__ int   g_off[N_NODES + 1];
__device__ int   g_cur[N_NODES];
__device__ int   g_srcs[N_EDGES];
__device__ int   g_bsum[128];

// ---------------- conv1: 16->16, k=5, pad=2, relu, maxpool2 ----------------
// grid (32, 64) blocks of 256. Tile: 128 pooled outputs = 256 conv outputs.
__global__ void conv1_pool_kernel(const float* __restrict__ x,
                                  const float* __restrict__ w,
                                  const float* __restrict__ b) {
    __shared__ float sx[16][260];
    __shared__ float sw[16 * 16 * 5];
    __shared__ float sb[16];
    const int tile = blockIdx.x, bb = blockIdx.y, tid = threadIdx.x;
    const int t0 = tile * 256 - 2;

    for (int i = tid; i < 16 * 260; i += 256) {
        int ci = i / 260, j = i - ci * 260;
        int t = t0 + j;
        sx[ci][j] = (t >= 0 && t < T_IN) ? x[(bb * 16 + ci) * T_IN + t] : 0.f;
    }
    for (int i = tid; i < 1280; i += 256) sw[i] = w[i];
    if (tid < 16) sb[tid] = b[tid];
    __syncthreads();

    const int tp  = tid & 127;
    const int cob = tid >> 7;            // 0 or 1
    const int p0  = 2 * tp;

    float a0[8], a1[8];
#pragma unroll
    for (int u = 0; u < 8; u++) { a0[u] = 0.f; a1[u] = 0.f; }

#pragma unroll
    for (int ci = 0; ci < 16; ci++) {
        float v0 = sx[ci][p0 + 0], v1 = sx[ci][p0 + 1], v2 = sx[ci][p0 + 2];
        float v3 = sx[ci][p0 + 3], v4 = sx[ci][p0 + 4], v5 = sx[ci][p0 + 5];
#pragma unroll
        for (int u = 0; u < 8; u++) {
            int co = cob + 2 * u;
            const float* wp = &sw[(co * 16 + ci) * 5];
            float w0 = wp[0], w1 = wp[1], w2 = wp[2], w3 = wp[3], w4 = wp[4];
            a0[u] += w0 * v0 + w1 * v1 + w2 * v2 + w3 * v3 + w4 * v4;
            a1[u] += w0 * v1 + w1 * v2 + w2 * v3 + w3 * v4 + w4 * v5;
        }
    }
#pragma unroll
    for (int u = 0; u < 8; u++) {
        int co = cob + 2 * u;
        float r = fmaxf(fmaxf(a0[u], a1[u]) + sb[co], 0.f);
        g_h1[(bb * 16 + co) * T2 + tile * 128 + tp] = r;
    }
}

// ---------------- conv2: 16->32, k=5, pad=2, relu, maxpool2, transpose write ----------------
// grid (16, 64) blocks of 256. Writes node-major feat via shared staging.
__global__ void conv2_pool_kernel(const float* __restrict__ w,
                                  const float* __restrict__ b) {
    __shared__ float sx[16][260];
    __shared__ float sw[32 * 16 * 5];
    __shared__ float sb[32];
    __shared__ float so[128 * 33];       // padded staging for transposed write
    const int tile = blockIdx.x, bb = blockIdx.y, tid = threadIdx.x;
    const int t0 = tile * 256 - 2;

    for (int i = tid; i < 16 * 260; i += 256) {
        int ci = i / 260, j = i - ci * 260;
        int t = t0 + j;
        sx[ci][j] = (t >= 0 && t < T2) ? g_h1[(bb * 16 + ci) * T2 + t] : 0.f;
    }
    for (int i = tid; i < 2560; i += 256) sw[i] = w[i];
    if (tid < 32) sb[tid] = b[tid];
    __syncthreads();

    const int tp  = tid & 127;
    const int cob = tid >> 7;            // 0 or 1
    const int p0  = 2 * tp;

    float a0[16], a1[16];
#pragma unroll
    for (int u = 0; u < 16; u++) { a0[u] = 0.f; a1[u] = 0.f; }

#pragma unroll
    for (int ci = 0; ci < 16; ci++) {
        float v0 = sx[ci][p0 + 0], v1 = sx[ci][p0 + 1], v2 = sx[ci][p0 + 2];
        float v3 = sx[ci][p0 + 3], v4 = sx[ci][p0 + 4], v5 = sx[ci][p0 + 5];
#pragma unroll
        for (int u = 0; u < 16; u++) {
            int co = cob + 2 * u;
            const float* wp = &sw[(co * 16 + ci) * 5];
            float w0 = wp[0], w1 = wp[1], w2 = wp[2], w3 = wp[3], w4 = wp[4];
            a0[u] += w0 * v0 + w1 * v1 + w2 * v2 + w3 * v3 + w4 * v4;
            a1[u] += w0 * v1 + w1 * v2 + w2 * v3 + w3 * v4 + w4 * v5;
        }
    }
#pragma unroll
    for (int u = 0; u < 16; u++) {
        int co = cob + 2 * u;
        so[tp * 33 + co] = fmaxf(fmaxf(a0[u], a1[u]) + sb[co], 0.f);
    }
    __syncthreads();

    const int node_base = bb * T4 + tile * 128;
    for (int i = tid; i < 128 * 32; i += 256) {
        int lp = i >> 5, co = i & 31;
        g_feat[(node_base + lp) * 32 + co] = so[lp * 33 + co];
    }
}

// ---------------- CSR build: histogram, scan, placement ----------------
__global__ void zero_cnt_kernel() {
    int i = blockIdx.x * blockDim.x + threadIdx.x;
    if (i < N_NODES) g_cnt[i] = 0;
}

__global__ void hist_kernel(const int* __restrict__ col) {
    int e = blockIdx.x * blockDim.x + threadIdx.x;
    if (e < N_EDGES) atomicAdd(&g_cnt[col[e]], 1);
}

__global__ void dis_kernel() {
    int i = blockIdx.x * blockDim.x + threadIdx.x;
    if (i < N_NODES) g_dis[i] = rsqrtf((float)(g_cnt[i] + 1));   // +1 = self loop
}

// 128 blocks x 256 threads x 4 elems
__global__ void scan1_kernel() {
    __shared__ int ss[256];
    const int tid = threadIdx.x;
    const int base = blockIdx.x * 1024 + tid * 4;
    int v0 = g_cnt[base], v1 = g_cnt[base + 1], v2 = g_cnt[base + 2], v3 = g_cnt[base + 3];
    int tsum = v0 + v1 + v2 + v3;
    ss[tid] = tsum;
    __syncthreads();
    for (int d = 1; d < 256; d <<= 1) {
        int t = (tid >= d) ? ss[tid - d] : 0;
        __syncthreads();
        ss[tid] += t;
        __syncthreads();
    }
    int excl = ss[tid] - tsum;
    g_off[base]     = excl;
    g_off[base + 1] = excl + v0;
    g_off[base + 2] = excl + v0 + v1;
    g_off[base + 3] = excl + v0 + v1 + v2;
    if (tid == 255) g_bsum[blockIdx.x] = ss[255];
}

__global__ void scan2_kernel() {
    __shared__ int ss[128];
    const int tid = threadIdx.x;
    int v = g_bsum[tid];
    ss[tid] = v;
    __syncthreads();
    for (int d = 1; d < 128; d <<= 1) {
        int t = (tid >= d) ? ss[tid - d] : 0;
        __syncthreads();
        ss[tid] += t;
        __syncthreads();
    }
    g_bsum[tid] = ss[tid] - v;   // exclusive prefix of block sums
}

__global__ void scan3_kernel() {
    int i = blockIdx.x * blockDim.x + threadIdx.x;
    if (i < N_NODES) {
        int o = g_off[i] + g_bsum[i >> 10];
        g_off[i] = o;
        g_cur[i] = o;
        if (i == 0) g_off[N_NODES] = N_EDGES;
    }
}

__global__ void place_kernel(const int* __restrict__ row, const int* __restrict__ col) {
    int e = blockIdx.x * blockDim.x + threadIdx.x;
    if (e < N_EDGES) {
        int c = col[e];
        int p = atomicAdd(&g_cur[c], 1);
        g_srcs[p] = row[e];
    }
}

// ---------------- xw: y[n] = dis[n] * (f[n] @ W), W is [IN x 64] ----------------
// Input global selected by IN: 32 -> g_feat, 64 -> g_g1. (Never pass device
// globals as host-side kernel arguments.)
template <int IN>
__global__ void xw_kernel(const float* __restrict__ W) {
    const float* f = (IN == 32) ? g_feat : g_g1;
    __shared__ float sW[IN * 64];
    __shared__ float sf[4][IN];
    const int tid = threadIdx.x;
    const int n0 = blockIdx.x * 4;
    for (int i = tid; i < IN * 64; i += 256) sW[i] = W[i];
    for (int i = tid; i < 4 * IN; i += 256) {
        int ln = i / IN, c = i - ln * IN;
        sf[ln][c] = f[(n0 + ln) * IN + c];
    }
    __syncthreads();
    const int ln = tid >> 6, oc = tid & 63;
    const int n = n0 + ln;
    float acc = 0.f;
#pragma unroll
    for (int k = 0; k < IN; k++) acc += sf[ln][k] * sW[k * 64 + oc];
    g_y[n * 64 + oc] = acc * g_dis[n];
}

// ---------------- gather: out[i] = relu(dis[i]*(y[i] + sum_{j->i} y[j]) + bias) ----------------
// one warp per node; grid = N/8 blocks of 256. LAYER selects output global.
template <int LAYER>
__global__ void gather_kernel(const float* __restrict__ bias) {
    const float* __restrict__ y = g_y;
    float* __restrict__ out = (LAYER == 1) ? g_g1 : g_g2;
    const int gw = (blockIdx.x * 256 + threadIdx.x) >> 5;
    const int lane = threadIdx.x & 31;
    float a0 = y[gw * 64 + lane];          // self loop
    float a1 = y[gw * 64 + 32 + lane];
    int p = g_off[gw];
    const int e = g_off[gw + 1];
    for (; p + 4 <= e; p += 4) {
        int j0 = __ldg(&g_srcs[p]),     j1 = __ldg(&g_srcs[p + 1]);
        int j2 = __ldg(&g_srcs[p + 2]), j3 = __ldg(&g_srcs[p + 3]);
        float b00 = __ldg(&y[j0 * 64 + lane]),      b01 = __ldg(&y[j0 * 64 + 32 + lane]);
        float b10 = __ldg(&y[j1 * 64 + lane]),      b11 = __ldg(&y[j1 * 64 + 32 + lane]);
        float b20 = __ldg(&y[j2 * 64 + lane]),      b21 = __ldg(&y[j2 * 64 + 32 + lane]);
        float b30 = __ldg(&y[j3 * 64 + lane]),      b31 = __ldg(&y[j3 * 64 + 32 + lane]);
        a0 += (b00 + b10) + (b20 + b30);
        a1 += (b01 + b11) + (b21 + b31);
    }
    for (; p < e; p++) {
        int j = __ldg(&g_srcs[p]);
        a0 += __ldg(&y[j * 64 + lane]);
        a1 += __ldg(&y[j * 64 + 32 + lane]);
    }
    const float di = g_dis[gw];
    out[gw * 64 + lane]      = fmaxf(fmaf(di, a0, bias[lane]), 0.f);
    out[gw * 64 + 32 + lane] = fmaxf(fmaf(di, a1, bias[32 + lane]), 0.f);
}

// ---------------- mean pool over T4 nodes per batch + classifier ----------------
// grid = BATCH blocks of 256
__global__ void pool_cls_kernel(const float* __restrict__ clsw,
                                const float* __restrict__ clsb,
                                float* __restrict__ out) {
    __shared__ float sp[256];
    __shared__ float pooled[64];
    const int b = blockIdx.x, tid = threadIdx.x;
    const int c = tid & 63, q = tid >> 6;
    float s = 0.f;
    for (int n = q; n < T4; n += 4)
        s += g_g2[(b * T4 + n) * 64 + c];
    sp[tid] = s;
    __syncthreads();
    if (tid < 64)
        pooled[tid] = (sp[tid] + sp[tid + 64] + sp[tid + 128] + sp[tid + 192]) * (1.f / (float)T4);
    __syncthreads();
    if (tid < OUTC) {
        float acc = clsb[tid];
#pragma unroll
        for (int cc = 0; cc < 64; cc++) acc += pooled[cc] * clsw[cc * OUTC + tid];
        out[b * OUTC + tid] = acc;
    }
}

// ---------------- launch ----------------
extern "C" void kernel_launch(void* const* d_in, const int* in_sizes, int n_in,
                              void* d_out, int out_size) {
    // Size-based input dispatch (order-independent), with positional fallback.
    const float* x       = nullptr;
    const int*   ei      = nullptr;
    const float* conv1_w = nullptr; const float* conv1_b = nullptr;
    const float* conv2_w = nullptr; const float* conv2_b = nullptr;
    const float* gcn1_w  = nullptr; const float* gcn1_b  = nullptr;
    const float* gcn2_w  = nullptr; const float* gcn2_b  = nullptr;
    const float* cls_w   = nullptr; const float* cls_b   = nullptr;

    for (int i = 0; i < n_in; i++) {
        switch (in_sizes[i]) {
            case BATCH * 16 * T_IN:   x       = (const float*)d_in[i]; break;  // 8388608
            case 2 * N_EDGES:         ei      = (const int*)  d_in[i]; break;  // 4194304
            case 16 * 16 * 5:         conv1_w = (const float*)d_in[i]; break;  // 1280
            case 16:                  conv1_b = (const float*)d_in[i]; break;
            case 32 * 16 * 5:         conv2_w = (const float*)d_in[i]; break;  // 2560
            case 32:                  conv2_b = (const float*)d_in[i]; break;
            case 32 * HID:            gcn1_w  = (const float*)d_in[i]; break;  // 2048
            case HID * HID:           gcn2_w  = (const float*)d_in[i]; break;  // 4096
            case HID * OUTC:          cls_w   = (const float*)d_in[i]; break;  // 640
            case OUTC:                cls_b   = (const float*)d_in[i]; break;  // 10
            case HID:                                                          // 64 (twice)
                if (!gcn1_b) gcn1_b = (const float*)d_in[i];
                else         gcn2_b = (const float*)d_in[i];
                break;
            default: break;
        }
    }
    if (!x || !ei || !conv1_w || !conv2_w || !gcn1_w || !gcn2_w || !cls_w) {
        // positional fallback (setup_inputs order)
        x       = (const float*)d_in[0];  ei      = (const int*)  d_in[1];
        conv1_w = (const float*)d_in[2];  conv1_b = (const float*)d_in[3];
        conv2_w = (const float*)d_in[4];  conv2_b = (const float*)d_in[5];
        gcn1_w  = (const float*)d_in[6];  gcn1_b  = (const float*)d_in[7];
        gcn2_w  = (const float*)d_in[8];  gcn2_b  = (const float*)d_in[9];
        cls_w   = (const float*)d_in[10]; cls_b   = (const float*)d_in[11];
    }

    float* out = (float*)d_out;
    const int* e_row = ei;              // sources
    const int* e_col = ei + N_EDGES;    // targets

    // CSR build for the graph (also yields degrees)
    zero_cnt_kernel<<<N_NODES / 256, 256>>>();
    hist_kernel<<<N_EDGES / 256, 256>>>(e_col);
    dis_kernel<<<N_NODES / 256, 256>>>();
    scan1_kernel<<<128, 256>>>();
    scan2_kernel<<<1, 128>>>();
    scan3_kernel<<<N_NODES / 256, 256>>>();
    place_kernel<<<N_EDGES / 256, 256>>>(e_row, e_col);

    // temporal conv stack
    {
        dim3 g1(T2 / 128, BATCH);
        conv1_pool_kernel<<<g1, 256>>>(x, conv1_w, conv1_b);
        dim3 g2(T4 / 128, BATCH);
        conv2_pool_kernel<<<g2, 256>>>(conv2_w, conv2_b);
    }

    // GCN layer 1
    xw_kernel<32><<<N_NODES / 4, 256>>>(gcn1_w);
    gather_kernel<1><<<N_NODES / 8, 256>>>(gcn1_b);

    // GCN layer 2
    xw_kernel<64><<<N_NODES / 4, 256>>>(gcn2_w);
    gather_kernel<2><<<N_NODES / 8, 256>>>(gcn2_b);

    // mean pool + classifier
    pool_cls_kernel<<<BATCH, 256>>>(cls_w, cls_b, out);
}

// round 4
// speedup vs baseline: 1.2878x; 1.2878x over previous
#include <cuda_runtime.h>
#include <cuda_bf16.h>

// ---------------- problem constants ----------------
#define BATCH   64
#define T_IN    8192
#define T2      4096        // after pool1
#define T4      2048        // after pool2
#define N_NODES 131072      // BATCH * T4
#define N_EDGES 2097152
#define HID     64
#define OUTC    10

typedef unsigned long long u64;

// ---------------- f32x2 packed helpers (Blackwell) ----------------
__device__ __forceinline__ u64 pk2(float lo, float hi) {
    u64 r; asm("mov.b64 %0, {%1, %2};" : "=l"(r) : "f"(lo), "f"(hi)); return r;
}
__device__ __forceinline__ void upk2(u64 v, float& lo, float& hi) {
    asm("mov.b64 {%0, %1}, %2;" : "=f"(lo), "=f"(hi) : "l"(v));
}
__device__ __forceinline__ void fma2(u64& acc, u64 a, u64 b) {
    asm("fma.rn.f32x2 %0, %1, %2, %3;" : "=l"(acc) : "l"(a), "l"(b), "l"(acc));
}

// ---------------- scratch (device globals, no allocation) ----------------
// NOTE: referenced ONLY inside device code. Passing these as host-side kernel
// args silently passes the host shadow address (GB300 ATS reads zeros, no fault).
__device__ float g_h1[BATCH * 16 * T2];          // conv1 output pooled [b][c][t]
__device__ float g_feat[N_NODES * 32];           // conv2 output * dis, node-major
__device__ float g_z[N_NODES * 32];              // aggregated 32-dim features
__device__ float g_y[N_NODES * 64];              // dis * (g1 @ W2)
__device__ float g_g1[N_NODES * 64];             // gcn1 output
__device__ float g_g2[N_NODES * 64];             // gcn2 output
__device__ float g_dis[N_NODES];
__device__ int   g_cnt[N_NODES];
__device__ int   g_off[N_NODES + 1];
__device__ int   g_cur[N_NODES];
__device__ int   g_srcs[N_EDGES];
__device__ int   g_bsum[128];

// ---------------- conv1: 16->16, k=5, pad=2, relu, maxpool2 ----------------
__global__ void conv1_pool_kernel(const float* __restrict__ x,
                                  const float* __restrict__ w,
                                  const float* __restrict__ b) {
    __shared__ float sx[16][260];
    __shared__ float sw[16 * 16 * 5];
    __shared__ float sb[16];
    const int tile = blockIdx.x, bb = blockIdx.y, tid = threadIdx.x;
    const int t0 = tile * 256 - 2;

    for (int i = tid; i < 16 * 260; i += 256) {
        int ci = i / 260, j = i - ci * 260;
        int t = t0 + j;
        sx[ci][j] = (t >= 0 && t < T_IN) ? x[(bb * 16 + ci) * T_IN + t] : 0.f;
    }
    for (int i = tid; i < 1280; i += 256) sw[i] = w[i];
    if (tid < 16) sb[tid] = b[tid];
    __syncthreads();

    const int tp  = tid & 127;
    const int cob = tid >> 7;
    const int p0  = 2 * tp;

    float a0[8], a1[8];
#pragma unroll
    for (int u = 0; u < 8; u++) { a0[u] = 0.f; a1[u] = 0.f; }

#pragma unroll
    for (int ci = 0; ci < 16; ci++) {
        float v0 = sx[ci][p0 + 0], v1 = sx[ci][p0 + 1], v2 = sx[ci][p0 + 2];
        float v3 = sx[ci][p0 + 3], v4 = sx[ci][p0 + 4], v5 = sx[ci][p0 + 5];
#pragma unroll
        for (int u = 0; u < 8; u++) {
            int co = cob + 2 * u;
            const float* wp = &sw[(co * 16 + ci) * 5];
            float w0 = wp[0], w1 = wp[1], w2 = wp[2], w3 = wp[3], w4 = wp[4];
            a0[u] += w0 * v0 + w1 * v1 + w2 * v2 + w3 * v3 + w4 * v4;
            a1[u] += w0 * v1 + w1 * v2 + w2 * v3 + w3 * v4 + w4 * v5;
        }
    }
#pragma unroll
    for (int u = 0; u < 8; u++) {
        int co = cob + 2 * u;
        float r = fmaxf(fmaxf(a0[u], a1[u]) + sb[co], 0.f);
        g_h1[(bb * 16 + co) * T2 + tile * 128 + tp] = r;
    }
}

// ---------------- conv2: 16->32, relu, pool, transpose, * dis ----------------
__global__ void conv2_pool_kernel(const float* __restrict__ w,
                                  const float* __restrict__ b) {
    __shared__ float sx[16][260];
    __shared__ float sw[32 * 16 * 5];
    __shared__ float sb[32];
    __shared__ float so[128 * 33];
    const int tile = blockIdx.x, bb = blockIdx.y, tid = threadIdx.x;
    const int t0 = tile * 256 - 2;

    for (int i = tid; i < 16 * 260; i += 256) {
        int ci = i / 260, j = i - ci * 260;
        int t = t0 + j;
        sx[ci][j] = (t >= 0 && t < T2) ? g_h1[(bb * 16 + ci) * T2 + t] : 0.f;
    }
    for (int i = tid; i < 2560; i += 256) sw[i] = w[i];
    if (tid < 32) sb[tid] = b[tid];
    __syncthreads();

    const int tp  = tid & 127;
    const int cob = tid >> 7;
    const int p0  = 2 * tp;

    float a0[16], a1[16];
#pragma unroll
    for (int u = 0; u < 16; u++) { a0[u] = 0.f; a1[u] = 0.f; }

#pragma unroll
    for (int ci = 0; ci < 16; ci++) {
        float v0 = sx[ci][p0 + 0], v1 = sx[ci][p0 + 1], v2 = sx[ci][p0 + 2];
        float v3 = sx[ci][p0 + 3], v4 = sx[ci][p0 + 4], v5 = sx[ci][p0 + 5];
#pragma unroll
        for (int u = 0; u < 16; u++) {
            int co = cob + 2 * u;
            const float* wp = &sw[(co * 16 + ci) * 5];
            float w0 = wp[0], w1 = wp[1], w2 = wp[2], w3 = wp[3], w4 = wp[4];
            a0[u] += w0 * v0 + w1 * v1 + w2 * v2 + w3 * v3 + w4 * v4;
            a1[u] += w0 * v1 + w1 * v2 + w2 * v3 + w3 * v4 + w4 * v5;
        }
    }
#pragma unroll
    for (int u = 0; u < 16; u++) {
        int co = cob + 2 * u;
        so[tp * 33 + co] = fmaxf(fmaxf(a0[u], a1[u]) + sb[co], 0.f);
    }
    __syncthreads();

    const int node_base = bb * T4 + tile * 128;
    for (int i = tid; i < 128 * 32; i += 256) {
        int lp = i >> 5, co = i & 31;
        // pre-scale by dis[node]: fuses the per-source GCN normalization
        g_feat[(node_base + lp) * 32 + co] = so[lp * 33 + co] * __ldg(&g_dis[node_base + lp]);
    }
}

// ---------------- CSR build ----------------
__global__ void zero_cnt_kernel() {
    int i = blockIdx.x * blockDim.x + threadIdx.x;
    if (i < N_NODES) g_cnt[i] = 0;
}

__global__ void hist_kernel(const int* __restrict__ col) {
    int e = blockIdx.x * blockDim.x + threadIdx.x;
    if (e < N_EDGES) atomicAdd(&g_cnt[col[e]], 1);
}

__global__ void dis_kernel() {
    int i = blockIdx.x * blockDim.x + threadIdx.x;
    if (i < N_NODES) g_dis[i] = rsqrtf((float)(g_cnt[i] + 1));   // +1 = self loop
}

__global__ void scan1_kernel() {
    __shared__ int ss[256];
    const int tid = threadIdx.x;
    const int base = blockIdx.x * 1024 + tid * 4;
    int v0 = g_cnt[base], v1 = g_cnt[base + 1], v2 = g_cnt[base + 2], v3 = g_cnt[base + 3];
    int tsum = v0 + v1 + v2 + v3;
    ss[tid] = tsum;
    __syncthreads();
    for (int d = 1; d < 256; d <<= 1) {
        int t = (tid >= d) ? ss[tid - d] : 0;
        __syncthreads();
        ss[tid] += t;
        __syncthreads();
    }
    int excl = ss[tid] - tsum;
    g_off[base]     = excl;
    g_off[base + 1] = excl + v0;
    g_off[base + 2] = excl + v0 + v1;
    g_off[base + 3] = excl + v0 + v1 + v2;
    if (tid == 255) g_bsum[blockIdx.x] = ss[255];
}

__global__ void scan2_kernel() {
    __shared__ int ss[128];
    const int tid = threadIdx.x;
    int v = g_bsum[tid];
    ss[tid] = v;
    __syncthreads();
    for (int d = 1; d < 128; d <<= 1) {
        int t = (tid >= d) ? ss[tid - d] : 0;
        __syncthreads();
        ss[tid] += t;
        __syncthreads();
    }
    g_bsum[tid] = ss[tid] - v;
}

__global__ void scan3_kernel() {
    int i = blockIdx.x * blockDim.x + threadIdx.x;
    if (i < N_NODES) {
        int o = g_off[i] + g_bsum[i >> 10];
        g_off[i] = o;
        g_cur[i] = o;
        if (i == 0) g_off[N_NODES] = N_EDGES;
    }
}

__global__ void place_kernel(const int* __restrict__ row, const int* __restrict__ col) {
    int e = blockIdx.x * blockDim.x + threadIdx.x;
    if (e < N_EDGES) {
        int c = col[e];
        int p = atomicAdd(&g_cur[c], 1);
        g_srcs[p] = row[e];
    }
}

// ---------------- gather32: z[i] = dis_i * (feat~[i] + sum_{j->i} feat~[j]) ----------------
// feat~ is already dis-scaled. One warp per node, lane = feature channel.
__global__ void gather32_kernel() {
    const int gw = (blockIdx.x * 256 + threadIdx.x) >> 5;
    const int lane = threadIdx.x & 31;
    const float* __restrict__ y = g_feat;
    float a = y[gw * 32 + lane];           // self loop (dis_i * feat_i)
    int p = g_off[gw];
    const int e = g_off[gw + 1];
    for (; p + 8 <= e; p += 8) {
        int j0 = __ldg(&g_srcs[p + 0]), j1 = __ldg(&g_srcs[p + 1]);
        int j2 = __ldg(&g_srcs[p + 2]), j3 = __ldg(&g_srcs[p + 3]);
        int j4 = __ldg(&g_srcs[p + 4]), j5 = __ldg(&g_srcs[p + 5]);
        int j6 = __ldg(&g_srcs[p + 6]), j7 = __ldg(&g_srcs[p + 7]);
        float b0 = __ldg(&y[j0 * 32 + lane]), b1 = __ldg(&y[j1 * 32 + lane]);
        float b2 = __ldg(&y[j2 * 32 + lane]), b3 = __ldg(&y[j3 * 32 + lane]);
        float b4 = __ldg(&y[j4 * 32 + lane]), b5 = __ldg(&y[j5 * 32 + lane]);
        float b6 = __ldg(&y[j6 * 32 + lane]), b7 = __ldg(&y[j7 * 32 + lane]);
        a += ((b0 + b1) + (b2 + b3)) + ((b4 + b5) + (b6 + b7));
    }
    for (; p < e; p++) {
        int j = __ldg(&g_srcs[p]);
        a += __ldg(&y[j * 32 + lane]);
    }
    g_z[gw * 32 + lane] = a * g_dis[gw];
}

// ---------------- xw: register-blocked GEMV with f32x2 ----------------
// lane = node; 64 output channels in 32 packed accumulators.
// MODE 1: g_g1 = relu(g_z @ W + bias)      (IN = 32)
// MODE 2: g_y  = dis * (g_g1 @ W)          (IN = 64)
template <int IN, int MODE>
__global__ void xw_kernel(const float* __restrict__ W, const float* __restrict__ bias) {
    __shared__ __align__(16) u64 sW2[IN * 32];   // row k: 32 packed (oc2j, oc2j+1)
    const int tid = threadIdx.x;
    const float2* Wf2 = (const float2*)W;
    for (int i = tid; i < IN * 32; i += 256) {
        float2 wv = Wf2[i];
        sW2[i] = pk2(wv.x, wv.y);
    }
    __syncthreads();

    const int lane = tid & 31, wp = tid >> 5;
    const int n = blockIdx.x * 256 + wp * 32 + lane;
    const float* __restrict__ f = (MODE == 1) ? g_z : g_g1;

    u64 acc[32];
#pragma unroll
    for (int j = 0; j < 32; j++) acc[j] = 0ull;

    const float4* fv = (const float4*)(f + (size_t)n * IN);
#pragma unroll
    for (int kc = 0; kc < IN / 4; kc++) {
        float4 xv = fv[kc];
        float xs0 = xv.x, xs1 = xv.y, xs2 = xv.z, xs3 = xv.w;
#pragma unroll
        for (int kk = 0; kk < 4; kk++) {
            float xk = (kk == 0) ? xs0 : (kk == 1) ? xs1 : (kk == 2) ? xs2 : xs3;
            u64 x2 = pk2(xk, xk);
            const ulonglong2* wrow = (const ulonglong2*)&sW2[(kc * 4 + kk) * 32];
#pragma unroll
            for (int j = 0; j < 16; j++) {
                ulonglong2 wv = wrow[j];
                fma2(acc[2 * j],     x2, wv.x);
                fma2(acc[2 * j + 1], x2, wv.y);
            }
        }
    }

    if (MODE == 1) {
        float* o = g_g1 + (size_t)n * 64;
#pragma unroll
        for (int j = 0; j < 16; j++) {
            float l0, h0, l1, h1;
            upk2(acc[2 * j], l0, h0);
            upk2(acc[2 * j + 1], l1, h1);
            float4 r;
            r.x = fmaxf(l0 + __ldg(&bias[4 * j + 0]), 0.f);
            r.y = fmaxf(h0 + __ldg(&bias[4 * j + 1]), 0.f);
            r.z = fmaxf(l1 + __ldg(&bias[4 * j + 2]), 0.f);
            r.w = fmaxf(h1 + __ldg(&bias[4 * j + 3]), 0.f);
            ((float4*)o)[j] = r;
        }
    } else {
        const float di = g_dis[n];
        float* o = g_y + (size_t)n * 64;
#pragma unroll
        for (int j = 0; j < 16; j++) {
            float l0, h0, l1, h1;
            upk2(acc[2 * j], l0, h0);
            upk2(acc[2 * j + 1], l1, h1);
            float4 r;
            r.x = l0 * di; r.y = h0 * di; r.z = l1 * di; r.w = h1 * di;
            ((float4*)o)[j] = r;
        }
    }
}

// ---------------- gather64: g2[i] = relu(dis_i*(y_i + sum y_j) + bias) ----------------
__global__ void gather64_kernel(const float* __restrict__ bias) {
    const float* __restrict__ y = g_y;
    const int gw = (blockIdx.x * 256 + threadIdx.x) >> 5;
    const int lane = threadIdx.x & 31;
    float a0 = y[gw * 64 + lane];
    float a1 = y[gw * 64 + 32 + lane];
    int p = g_off[gw];
    const int e = g_off[gw + 1];
    for (; p + 8 <= e; p += 8) {
        int j0 = __ldg(&g_srcs[p + 0]), j1 = __ldg(&g_srcs[p + 1]);
        int j2 = __ldg(&g_srcs[p + 2]), j3 = __ldg(&g_srcs[p + 3]);
        int j4 = __ldg(&g_srcs[p + 4]), j5 = __ldg(&g_srcs[p + 5]);
        int j6 = __ldg(&g_srcs[p + 6]), j7 = __ldg(&g_srcs[p + 7]);
        float b00 = __ldg(&y[j0 * 64 + lane]), b01 = __ldg(&y[j0 * 64 + 32 + lane]);
        float b10 = __ldg(&y[j1 * 64 + lane]), b11 = __ldg(&y[j1 * 64 + 32 + lane]);
        float b20 = __ldg(&y[j2 * 64 + lane]), b21 = __ldg(&y[j2 * 64 + 32 + lane]);
        float b30 = __ldg(&y[j3 * 64 + lane]), b31 = __ldg(&y[j3 * 64 + 32 + lane]);
        float b40 = __ldg(&y[j4 * 64 + lane]), b41 = __ldg(&y[j4 * 64 + 32 + lane]);
        float b50 = __ldg(&y[j5 * 64 + lane]), b51 = __ldg(&y[j5 * 64 + 32 + lane]);
        float b60 = __ldg(&y[j6 * 64 + lane]), b61 = __ldg(&y[j6 * 64 + 32 + lane]);
        float b70 = __ldg(&y[j7 * 64 + lane]), b71 = __ldg(&y[j7 * 64 + 32 + lane]);
        a0 += ((b00 + b10) + (b20 + b30)) + ((b40 + b50) + (b60 + b70));
        a1 += ((b01 + b11) + (b21 + b31)) + ((b41 + b51) + (b61 + b71));
    }
    for (; p < e; p++) {
        int j = __ldg(&g_srcs[p]);
        a0 += __ldg(&y[j * 64 + lane]);
        a1 += __ldg(&y[j * 64 + 32 + lane]);
    }
    const float di = g_dis[gw];
    g_g2[gw * 64 + lane]      = fmaxf(fmaf(di, a0, __ldg(&bias[lane])), 0.f);
    g_g2[gw * 64 + 32 + lane] = fmaxf(fmaf(di, a1, __ldg(&bias[32 + lane])), 0.f);
}

// ---------------- mean pool + classifier ----------------
__global__ void pool_cls_kernel(const float* __restrict__ clsw,
                                const float* __restrict__ clsb,
                                float* __restrict__ out) {
    __shared__ float sp[256];
    __shared__ float pooled[64];
    const int b = blockIdx.x, tid = threadIdx.x;
    const int c = tid & 63, q = tid >> 6;
    float s = 0.f;
    for (int n = q; n < T4; n += 4)
        s += g_g2[((size_t)b * T4 + n) * 64 + c];
    sp[tid] = s;
    __syncthreads();
    if (tid < 64)
        pooled[tid] = (sp[tid] + sp[tid + 64] + sp[tid + 128] + sp[tid + 192]) * (1.f / (float)T4);
    __syncthreads();
    if (tid < OUTC) {
        float acc = clsb[tid];
#pragma unroll
        for (int cc = 0; cc < 64; cc++) acc += pooled[cc] * clsw[cc * OUTC + tid];
        out[b * OUTC + tid] = acc;
    }
}

// ---------------- launch ----------------
extern "C" void kernel_launch(void* const* d_in, const int* in_sizes, int n_in,
                              void* d_out, int out_size) {
    const float* x       = nullptr;
    const int*   ei      = nullptr;
    const float* conv1_w = nullptr; const float* conv1_b = nullptr;
    const float* conv2_w = nullptr; const float* conv2_b = nullptr;
    const float* gcn1_w  = nullptr; const float* gcn1_b  = nullptr;
    const float* gcn2_w  = nullptr; const float* gcn2_b  = nullptr;
    const float* cls_w   = nullptr; const float* cls_b   = nullptr;

    for (int i = 0; i < n_in; i++) {
        switch (in_sizes[i]) {
            case BATCH * 16 * T_IN:   x       = (const float*)d_in[i]; break;
            case 2 * N_EDGES:         ei      = (const int*)  d_in[i]; break;
            case 16 * 16 * 5:         conv1_w = (const float*)d_in[i]; break;
            case 16:                  conv1_b = (const float*)d_in[i]; break;
            case 32 * 16 * 5:         conv2_w = (const float*)d_in[i]; break;
            case 32:                  conv2_b = (const float*)d_in[i]; break;
            case 32 * HID:            gcn1_w  = (const float*)d_in[i]; break;
            case HID * HID:           gcn2_w  = (const float*)d_in[i]; break;
            case HID * OUTC:          cls_w   = (const float*)d_in[i]; break;
            case OUTC:                cls_b   = (const float*)d_in[i]; break;
            case HID:
                if (!gcn1_b) gcn1_b = (const float*)d_in[i];
                else         gcn2_b = (const float*)d_in[i];
                break;
            default: break;
        }
    }
    if (!x || !ei || !conv1_w || !conv2_w || !gcn1_w || !gcn2_w || !cls_w) {
        x       = (const float*)d_in[0];  ei      = (const int*)  d_in[1];
        conv1_w = (const float*)d_in[2];  conv1_b = (const float*)d_in[3];
        conv2_w = (const float*)d_in[4];  conv2_b = (const float*)d_in[5];
        gcn1_w  = (const float*)d_in[6];  gcn1_b  = (const float*)d_in[7];
        gcn2_w  = (const float*)d_in[8];  gcn2_b  = (const float*)d_in[9];
        cls_w   = (const float*)d_in[10]; cls_b   = (const float*)d_in[11];
    }

    float* out = (float*)d_out;
    const int* e_row = ei;
    const int* e_col = ei + N_EDGES;

    // CSR build (dis must precede conv2, which fuses the dis pre-scale)
    zero_cnt_kernel<<<N_NODES / 256, 256>>>();
    hist_kernel<<<N_EDGES / 256, 256>>>(e_col);
    dis_kernel<<<N_NODES / 256, 256>>>();
    scan1_kernel<<<128, 256>>>();
    scan2_kernel<<<1, 128>>>();
    scan3_kernel<<<N_NODES / 256, 256>>>();
    place_kernel<<<N_EDGES / 256, 256>>>(e_row, e_col);

    // temporal conv stack
    {
        dim3 g1(T2 / 128, BATCH);
        conv1_pool_kernel<<<g1, 256>>>(x, conv1_w, conv1_b);
        dim3 g2(T4 / 128, BATCH);
        conv2_pool_kernel<<<g2, 256>>>(conv2_w, conv2_b);
    }

    // GCN layer 1: aggregate 32-dim first, then matmul (+bias, relu)
    gather32_kernel<<<N_NODES / 8, 256>>>();
    xw_kernel<32, 1><<<N_NODES / 256, 256>>>(gcn1_w, gcn1_b);

    // GCN layer 2: matmul (dis-scaled), then aggregate 64-dim
    xw_kernel<64, 2><<<N_NODES / 256, 256>>>(gcn2_w, gcn2_b);
    gather64_kernel<<<N_NODES / 8, 256>>>(gcn2_b);

    // mean pool + classifier
    pool_cls_kernel<<<BATCH, 256>>>(cls_w, cls_b, out);
}

// round 5
// speedup vs baseline: 1.6973x; 1.3180x over previous
#include <cuda_runtime.h>
#include <cuda_bf16.h>
#include <cuda_fp16.h>

// ---------------- problem constants ----------------
#define BATCH   64
#define T_IN    8192
#define T2      4096        // after pool1
#define T4      2048        // after pool2
#define N_NODES 131072      // BATCH * T4
#define N_EDGES 2097152
#define HID     64
#define OUTC    10

typedef unsigned long long u64;

// ---------------- f32x2 packed helpers (Blackwell) ----------------
__device__ __forceinline__ u64 pk2(float lo, float hi) {
    u64 r; asm("mov.b64 %0, {%1, %2};" : "=l"(r) : "f"(lo), "f"(hi)); return r;
}
__device__ __forceinline__ void upk2(u64 v, float& lo, float& hi) {
    asm("mov.b64 {%0, %1}, %2;" : "=f"(lo), "=f"(hi) : "l"(v));
}
__device__ __forceinline__ void fma2(u64& acc, u64 a, u64 b) {
    asm("fma.rn.f32x2 %0, %1, %2, %3;" : "=l"(acc) : "l"(a), "l"(b), "l"(acc));
}

// ---------------- scratch (device globals, no allocation) ----------------
// NOTE: referenced ONLY inside device code (GB300 ATS silently reads the host
// shadow if passed as host-side kernel args).
__device__ float   g_h1[BATCH * 16 * T2];        // conv1 output pooled [b][c][t]
__device__ __half2 g_feat_h[N_NODES * 16];       // conv2 out * dis, fp16, node-major
__device__ float   g_z[N_NODES * 32];            // aggregated 32-dim features (fp32)
__device__ __half2 g_y_h[N_NODES * 32];          // dis * (g1 @ W2), fp16
__device__ float   g_g1[N_NODES * 64];           // gcn1 output (fp32)
__device__ float   g_g2[N_NODES * 64];           // gcn2 output (fp32)
__device__ float   g_dis[N_NODES];
__device__ int     g_cnt[N_NODES];
__device__ int     g_off[N_NODES + 1];
__device__ int     g_cur[N_NODES];
__device__ int     g_srcs[N_EDGES];
__device__ int     g_bsum[128];

// ---------------- conv1: 16->16, k=5, pad=2, relu, maxpool2 (FFMA2 co-pairs) ----
// grid (T2/256, BATCH) blocks of 256. Tile: 256 pooled outputs = 512 conv outputs.
// Each thread: 1 pooled position, all 16 co as 8 f32x2 pairs, 2 windows.
__global__ void conv1_pool_kernel(const float* __restrict__ x,
                                  const float* __restrict__ w,
                                  const float* __restrict__ b) {
    __shared__ float sx[16][516];
    __shared__ u64   sw2[8 * 16 * 5];   // [cp][ci][k] packed (co=2cp, 2cp+1)
    __shared__ float sb[16];
    const int tile = blockIdx.x, bb = blockIdx.y, tid = threadIdx.x;
    const int t0 = tile * 512 - 2;

    for (int i = tid; i < 16 * 516; i += 256) {
        int ci = i / 516, j = i - ci * 516;
        int t = t0 + j;
        sx[ci][j] = (t >= 0 && t < T_IN) ? x[(bb * 16 + ci) * T_IN + t] : 0.f;
    }
    for (int i = tid; i < 640; i += 256) {
        int cp = i / 80, r = i - cp * 80;
        sw2[i] = pk2(w[(2 * cp) * 80 + r], w[(2 * cp + 1) * 80 + r]);
    }
    if (tid < 16) sb[tid] = b[tid];
    __syncthreads();

    const int p0 = 2 * tid;
    u64 acc0[8], acc1[8];
#pragma unroll
    for (int cp = 0; cp < 8; cp++) { acc0[cp] = 0ull; acc1[cp] = 0ull; }

#pragma unroll
    for (int ci = 0; ci < 16; ci++) {
        float v0 = sx[ci][p0 + 0], v1 = sx[ci][p0 + 1], v2 = sx[ci][p0 + 2];
        float v3 = sx[ci][p0 + 3], v4 = sx[ci][p0 + 4], v5 = sx[ci][p0 + 5];
        u64 x0 = pk2(v0, v0), x1 = pk2(v1, v1), x2 = pk2(v2, v2);
        u64 x3 = pk2(v3, v3), x4 = pk2(v4, v4), x5 = pk2(v5, v5);
#pragma unroll
        for (int cp = 0; cp < 8; cp++) {
            const u64* wp = &sw2[(cp * 16 + ci) * 5];
            u64 w0 = wp[0], w1 = wp[1], w2 = wp[2], w3 = wp[3], w4 = wp[4];
            fma2(acc0[cp], w0, x0); fma2(acc1[cp], w0, x1);
            fma2(acc0[cp], w1, x1); fma2(acc1[cp], w1, x2);
            fma2(acc0[cp], w2, x2); fma2(acc1[cp], w2, x3);
            fma2(acc0[cp], w3, x3); fma2(acc1[cp], w3, x4);
            fma2(acc0[cp], w4, x4); fma2(acc1[cp], w4, x5);
        }
    }
    const int tbase = tile * 256 + tid;
#pragma unroll
    for (int cp = 0; cp < 8; cp++) {
        float e0, o0, e1, o1;
        upk2(acc0[cp], e0, o0);
        upk2(acc1[cp], e1, o1);
        float re = fmaxf(fmaxf(e0, e1) + sb[2 * cp], 0.f);
        float ro = fmaxf(fmaxf(o0, o1) + sb[2 * cp + 1], 0.f);
        g_h1[(bb * 16 + 2 * cp) * T2 + tbase]     = re;
        g_h1[(bb * 16 + 2 * cp + 1) * T2 + tbase] = ro;
    }
}

// ---------------- conv2: 16->32, relu, pool, *dis, fp16 transpose write --------
// grid (T4/128, BATCH) blocks of 256. 128 pooled positions x 2 co-groups.
__global__ void conv2_pool_kernel(const float* __restrict__ w,
                                  const float* __restrict__ b) {
    __shared__ float   sx[16][260];
    __shared__ u64     sw2[16 * 16 * 5];  // [cp][ci][k], co = 2cp, 2cp+1
    __shared__ float   sb[32];
    __shared__ __half2 so[128 * 17];      // staged (pos, co-pair) fp16
    const int tile = blockIdx.x, bb = blockIdx.y, tid = threadIdx.x;
    const int t0 = tile * 256 - 2;

    for (int i = tid; i < 16 * 260; i += 256) {
        int ci = i / 260, j = i - ci * 260;
        int t = t0 + j;
        sx[ci][j] = (t >= 0 && t < T2) ? g_h1[(bb * 16 + ci) * T2 + t] : 0.f;
    }
    for (int i = tid; i < 1280; i += 256) {
        int cp = i / 80, r = i - cp * 80;
        sw2[i] = pk2(w[(2 * cp) * 80 + r], w[(2 * cp + 1) * 80 + r]);
    }
    if (tid < 32) sb[tid] = b[tid];
    __syncthreads();

    const int tp  = tid & 127;
    const int cob = tid >> 7;            // 0 or 1 -> co-pairs [8*cob, 8*cob+8)
    const int p0  = 2 * tp;

    u64 acc0[8], acc1[8];
#pragma unroll
    for (int q = 0; q < 8; q++) { acc0[q] = 0ull; acc1[q] = 0ull; }

#pragma unroll
    for (int ci = 0; ci < 16; ci++) {
        float v0 = sx[ci][p0 + 0], v1 = sx[ci][p0 + 1], v2 = sx[ci][p0 + 2];
        float v3 = sx[ci][p0 + 3], v4 = sx[ci][p0 + 4], v5 = sx[ci][p0 + 5];
        u64 x0 = pk2(v0, v0), x1 = pk2(v1, v1), x2 = pk2(v2, v2);
        u64 x3 = pk2(v3, v3), x4 = pk2(v4, v4), x5 = pk2(v5, v5);
#pragma unroll
        for (int q = 0; q < 8; q++) {
            const u64* wp = &sw2[((cob * 8 + q) * 16 + ci) * 5];
            u64 w0 = wp[0], w1 = wp[1], w2 = wp[2], w3 = wp[3], w4 = wp[4];
            fma2(acc0[q], w0, x0); fma2(acc1[q], w0, x1);
            fma2(acc0[q], w1, x1); fma2(acc1[q], w1, x2);
            fma2(acc0[q], w2, x2); fma2(acc1[q], w2, x3);
            fma2(acc0[q], w3, x3); fma2(acc1[q], w3, x4);
            fma2(acc0[q], w4, x4); fma2(acc1[q], w4, x5);
        }
    }

    const int node_base = bb * T4 + tile * 128;
    const float d = __ldg(&g_dis[node_base + tp]);
#pragma unroll
    for (int q = 0; q < 8; q++) {
        int cp = cob * 8 + q;
        float e0, o0, e1, o1;
        upk2(acc0[q], e0, o0);
        upk2(acc1[q], e1, o1);
        float re = fmaxf(fmaxf(e0, e1) + sb[2 * cp], 0.f) * d;
        float ro = fmaxf(fmaxf(o0, o1) + sb[2 * cp + 1], 0.f) * d;
        so[tp * 17 + cp] = __floats2half2_rn(re, ro);
    }
    __syncthreads();

    for (int i = tid; i < 128 * 16; i += 256) {
        int lp = i >> 4, c = i & 15;
        g_feat_h[(node_base + lp) * 16 + c] = so[lp * 17 + c];
    }
}

// ---------------- CSR build ----------------
__global__ void zero_cnt_kernel() {
    int i = blockIdx.x * blockDim.x + threadIdx.x;
    if (i < N_NODES) g_cnt[i] = 0;
}

__global__ void hist_kernel(const int* __restrict__ col) {
    int e = blockIdx.x * blockDim.x + threadIdx.x;
    if (e < N_EDGES) atomicAdd(&g_cnt[col[e]], 1);
}

__global__ void dis_kernel() {
    int i = blockIdx.x * blockDim.x + threadIdx.x;
    if (i < N_NODES) g_dis[i] = rsqrtf((float)(g_cnt[i] + 1));   // +1 = self loop
}

__global__ void scan1_kernel() {
    __shared__ int ss[256];
    const int tid = threadIdx.x;
    const int base = blockIdx.x * 1024 + tid * 4;
    int v0 = g_cnt[base], v1 = g_cnt[base + 1], v2 = g_cnt[base + 2], v3 = g_cnt[base + 3];
    int tsum = v0 + v1 + v2 + v3;
    ss[tid] = tsum;
    __syncthreads();
    for (int d = 1; d < 256; d <<= 1) {
        int t = (tid >= d) ? ss[tid - d] : 0;
        __syncthreads();
        ss[tid] += t;
        __syncthreads();
    }
    int excl = ss[tid] - tsum;
    g_off[base]     = excl;
    g_off[base + 1] = excl + v0;
    g_off[base + 2] = excl + v0 + v1;
    g_off[base + 3] = excl + v0 + v1 + v2;
    if (tid == 255) g_bsum[blockIdx.x] = ss[255];
}

__global__ void scan2_kernel() {
    __shared__ int ss[128];
    const int tid = threadIdx.x;
    int v = g_bsum[tid];
    ss[tid] = v;
    __syncthreads();
    for (int d = 1; d < 128; d <<= 1) {
        int t = (tid >= d) ? ss[tid - d] : 0;
        __syncthreads();
        ss[tid] += t;
        __syncthreads();
    }
    g_bsum[tid] = ss[tid] - v;
}

__global__ void scan3_kernel() {
    int i = blockIdx.x * blockDim.x + threadIdx.x;
    if (i < N_NODES) {
        int o = g_off[i] + g_bsum[i >> 10];
        g_off[i] = o;
        g_cur[i] = o;
        if (i == 0) g_off[N_NODES] = N_EDGES;
    }
}

__global__ void place_kernel(const int* __restrict__ row, const int* __restrict__ col) {
    int e = blockIdx.x * blockDim.x + threadIdx.x;
    if (e < N_EDGES) {
        int c = col[e];
        int p = atomicAdd(&g_cur[c], 1);
        g_srcs[p] = row[e];
    }
}

// ---------------- gather32 (fp16): z[i] = dis_i * (feat~[i] + sum feat~[j]) ----
// One warp per node; half-warp per edge (2 edges in flight), lane&15 = half2 chan.
__global__ void gather32_kernel() {
    const int gw = (blockIdx.x * 256 + threadIdx.x) >> 5;
    const int lane = threadIdx.x & 31;
    const int hw = lane >> 4, c = lane & 15;
    const __half2* __restrict__ y = g_feat_h;

    float ax = 0.f, ay = 0.f;
    int p = g_off[gw];
    const int e = g_off[gw + 1];
    for (; p + 8 <= e; p += 8) {
        int j0 = __ldg(&g_srcs[p + 0 + hw]);
        int j1 = __ldg(&g_srcs[p + 2 + hw]);
        int j2 = __ldg(&g_srcs[p + 4 + hw]);
        int j3 = __ldg(&g_srcs[p + 6 + hw]);
        float2 v0 = __half22float2(__ldg(&y[j0 * 16 + c]));
        float2 v1 = __half22float2(__ldg(&y[j1 * 16 + c]));
        float2 v2 = __half22float2(__ldg(&y[j2 * 16 + c]));
        float2 v3 = __half22float2(__ldg(&y[j3 * 16 + c]));
        ax += (v0.x + v1.x) + (v2.x + v3.x);
        ay += (v0.y + v1.y) + (v2.y + v3.y);
    }
    for (; p + 2 <= e; p += 2) {
        int j = __ldg(&g_srcs[p + hw]);
        float2 v = __half22float2(__ldg(&y[j * 16 + c]));
        ax += v.x; ay += v.y;
    }
    if (p < e && hw == 0) {
        int j = __ldg(&g_srcs[p]);
        float2 v = __half22float2(__ldg(&y[j * 16 + c]));
        ax += v.x; ay += v.y;
    }
    // combine the two half-warps
    ax += __shfl_xor_sync(0xFFFFFFFFu, ax, 16);
    ay += __shfl_xor_sync(0xFFFFFFFFu, ay, 16);
    if (lane < 16) {
        float2 self = __half22float2(__ldg(&y[gw * 16 + c]));
        const float d = g_dis[gw];
        float2 r;
        r.x = (self.x + ax) * d;
        r.y = (self.y + ay) * d;
        ((float2*)g_z)[gw * 16 + c] = r;
    }
}

// ---------------- xw: register-blocked GEMV with f32x2 ----------------
// MODE 1: g_g1 = relu(g_z @ W + bias)        (IN = 32, fp32 out)
// MODE 2: g_y_h = dis * (g_g1 @ W)  (fp16)   (IN = 64)
template <int IN, int MODE>
__global__ void xw_kernel(const float* __restrict__ W, const float* __restrict__ bias) {
    __shared__ __align__(16) u64 sW2[IN * 32];   // row k: 32 packed (2j, 2j+1)
    const int tid = threadIdx.x;
    const float2* Wf2 = (const float2*)W;
    for (int i = tid; i < IN * 32; i += 256) {
        float2 wv = Wf2[i];
        sW2[i] = pk2(wv.x, wv.y);
    }
    __syncthreads();

    const int lane = tid & 31, wp = tid >> 5;
    const int n = blockIdx.x * 256 + wp * 32 + lane;
    const float* __restrict__ f = (MODE == 1) ? g_z : g_g1;

    u64 acc[32];
#pragma unroll
    for (int j = 0; j < 32; j++) acc[j] = 0ull;

    const float4* fv = (const float4*)(f + (size_t)n * IN);
#pragma unroll
    for (int kc = 0; kc < IN / 4; kc++) {
        float4 xv = fv[kc];
        float xs0 = xv.x, xs1 = xv.y, xs2 = xv.z, xs3 = xv.w;
#pragma unroll
        for (int kk = 0; kk < 4; kk++) {
            float xk = (kk == 0) ? xs0 : (kk == 1) ? xs1 : (kk == 2) ? xs2 : xs3;
            u64 x2 = pk2(xk, xk);
            const ulonglong2* wrow = (const ulonglong2*)&sW2[(kc * 4 + kk) * 32];
#pragma unroll
            for (int j = 0; j < 16; j++) {
                ulonglong2 wv = wrow[j];
                fma2(acc[2 * j],     x2, wv.x);
                fma2(acc[2 * j + 1], x2, wv.y);
            }
        }
    }

    if (MODE == 1) {
        float* o = g_g1 + (size_t)n * 64;
#pragma unroll
        for (int j = 0; j < 16; j++) {
            float l0, h0, l1, h1;
            upk2(acc[2 * j], l0, h0);
            upk2(acc[2 * j + 1], l1, h1);
            float4 r;
            r.x = fmaxf(l0 + __ldg(&bias[4 * j + 0]), 0.f);
            r.y = fmaxf(h0 + __ldg(&bias[4 * j + 1]), 0.f);
            r.z = fmaxf(l1 + __ldg(&bias[4 * j + 2]), 0.f);
            r.w = fmaxf(h1 + __ldg(&bias[4 * j + 3]), 0.f);
            ((float4*)o)[j] = r;
        }
    } else {
        const float di = g_dis[n];
        __half2* o = g_y_h + (size_t)n * 32;
#pragma unroll
        for (int q = 0; q < 8; q++) {   // 4 half2 per 16B store
            float l0, h0, l1, h1, l2, h2, l3, h3;
            upk2(acc[4 * q + 0], l0, h0);
            upk2(acc[4 * q + 1], l1, h1);
            upk2(acc[4 * q + 2], l2, h2);
            upk2(acc[4 * q + 3], l3, h3);
            __half2 a = __floats2half2_rn(l0 * di, h0 * di);
            __half2 b = __floats2half2_rn(l1 * di, h1 * di);
            __half2 cc = __floats2half2_rn(l2 * di, h2 * di);
            __half2 dd = __floats2half2_rn(l3 * di, h3 * di);
            uint4 pack;
            pack.x = *(unsigned*)&a;  pack.y = *(unsigned*)&b;
            pack.z = *(unsigned*)&cc; pack.w = *(unsigned*)&dd;
            ((uint4*)o)[q] = pack;
        }
    }
}

// ---------------- gather64 (fp16): g2[i] = relu(dis_i*(y_i + sum y_j) + bias) ----
// One warp per node; lane = half2 channel (32 half2 = 64 channels).
__global__ void gather64_kernel(const float* __restrict__ bias) {
    const __half2* __restrict__ y = g_y_h;
    const int gw = (blockIdx.x * 256 + threadIdx.x) >> 5;
    const int lane = threadIdx.x & 31;

    float2 a = __half22float2(__ldg(&y[gw * 32 + lane]));   // self loop
    int p = g_off[gw];
    const int e = g_off[gw + 1];
    for (; p + 8 <= e; p += 8) {
        int j0 = __ldg(&g_srcs[p + 0]), j1 = __ldg(&g_srcs[p + 1]);
        int j2 = __ldg(&g_srcs[p + 2]), j3 = __ldg(&g_srcs[p + 3]);
        int j4 = __ldg(&g_srcs[p + 4]), j5 = __ldg(&g_srcs[p + 5]);
        int j6 = __ldg(&g_srcs[p + 6]), j7 = __ldg(&g_srcs[p + 7]);
        float2 v0 = __half22float2(__ldg(&y[j0 * 32 + lane]));
        float2 v1 = __half22float2(__ldg(&y[j1 * 32 + lane]));
        float2 v2 = __half22float2(__ldg(&y[j2 * 32 + lane]));
        float2 v3 = __half22float2(__ldg(&y[j3 * 32 + lane]));
        float2 v4 = __half22float2(__ldg(&y[j4 * 32 + lane]));
        float2 v5 = __half22float2(__ldg(&y[j5 * 32 + lane]));
        float2 v6 = __half22float2(__ldg(&y[j6 * 32 + lane]));
        float2 v7 = __half22float2(__ldg(&y[j7 * 32 + lane]));
        a.x += ((v0.x + v1.x) + (v2.x + v3.x)) + ((v4.x + v5.x) + (v6.x + v7.x));
        a.y += ((v0.y + v1.y) + (v2.y + v3.y)) + ((v4.y + v5.y) + (v6.y + v7.y));
    }
    for (; p < e; p++) {
        int j = __ldg(&g_srcs[p]);
        float2 v = __half22float2(__ldg(&y[j * 32 + lane]));
        a.x += v.x; a.y += v.y;
    }
    const float d = g_dis[gw];
    float2 bb = ((const float2*)bias)[lane];
    float2 r;
    r.x = fmaxf(fmaf(d, a.x, bb.x), 0.f);
    r.y = fmaxf(fmaf(d, a.y, bb.y), 0.f);
    ((float2*)g_g2)[gw * 32 + lane] = r;
}

// ---------------- mean pool + classifier ----------------
__global__ void pool_cls_kernel(const float* __restrict__ clsw,
                                const float* __restrict__ clsb,
                                float* __restrict__ out) {
    __shared__ float sp[256];
    __shared__ float pooled[64];
    const int b = blockIdx.x, tid = threadIdx.x;
    const int c = tid & 63, q = tid >> 6;
    float s = 0.f;
    for (int n = q; n < T4; n += 4)
        s += g_g2[((size_t)b * T4 + n) * 64 + c];
    sp[tid] = s;
    __syncthreads();
    if (tid < 64)
        pooled[tid] = (sp[tid] + sp[tid + 64] + sp[tid + 128] + sp[tid + 192]) * (1.f / (float)T4);
    __syncthreads();
    if (tid < OUTC) {
        float acc = clsb[tid];
#pragma unroll
        for (int cc = 0; cc < 64; cc++) acc += pooled[cc] * clsw[cc * OUTC + tid];
        out[b * OUTC + tid] = acc;
    }
}

// ---------------- launch ----------------
extern "C" void kernel_launch(void* const* d_in, const int* in_sizes, int n_in,
                              void* d_out, int out_size) {
    const float* x       = nullptr;
    const int*   ei      = nullptr;
    const float* conv1_w = nullptr; const float* conv1_b = nullptr;
    const float* conv2_w = nullptr; const float* conv2_b = nullptr;
    const float* gcn1_w  = nullptr; const float* gcn1_b  = nullptr;
    const float* gcn2_w  = nullptr; const float* gcn2_b  = nullptr;
    const float* cls_w   = nullptr; const float* cls_b   = nullptr;

    for (int i = 0; i < n_in; i++) {
        switch (in_sizes[i]) {
            case BATCH * 16 * T_IN:   x       = (const float*)d_in[i]; break;
            case 2 * N_EDGES:         ei      = (const int*)  d_in[i]; break;
            case 16 * 16 * 5:         conv1_w = (const float*)d_in[i]; break;
            case 16:                  conv1_b = (const float*)d_in[i]; break;
            case 32 * 16 * 5:         conv2_w = (const float*)d_in[i]; break;
            case 32:                  conv2_b = (const float*)d_in[i]; break;
            case 32 * HID:            gcn1_w  = (const float*)d_in[i]; break;
            case HID * HID:           gcn2_w  = (const float*)d_in[i]; break;
            case HID * OUTC:          cls_w   = (const float*)d_in[i]; break;
            case OUTC:                cls_b   = (const float*)d_in[i]; break;
            case HID:
                if (!gcn1_b) gcn1_b = (const float*)d_in[i];
                else         gcn2_b = (const float*)d_in[i];
                break;
            default: break;
        }
    }
    if (!x || !ei || !conv1_w || !conv2_w || !gcn1_w || !gcn2_w || !cls_w) {
        x       = (const float*)d_in[0];  ei      = (const int*)  d_in[1];
        conv1_w = (const float*)d_in[2];  conv1_b = (const float*)d_in[3];
        conv2_w = (const float*)d_in[4];  conv2_b = (const float*)d_in[5];
        gcn1_w  = (const float*)d_in[6];  gcn1_b  = (const float*)d_in[7];
        gcn2_w  = (const float*)d_in[8];  gcn2_b  = (const float*)d_in[9];
        cls_w   = (const float*)d_in[10]; cls_b   = (const float*)d_in[11];
    }

    float* out = (float*)d_out;
    const int* e_row = ei;
    const int* e_col = ei + N_EDGES;

    // CSR build (dis must precede conv2, which fuses the dis pre-scale)
    zero_cnt_kernel<<<N_NODES / 256, 256>>>();
    hist_kernel<<<N_EDGES / 256, 256>>>(e_col);
    dis_kernel<<<N_NODES / 256, 256>>>();
    scan1_kernel<<<128, 256>>>();
    scan2_kernel<<<1, 128>>>();
    scan3_kernel<<<N_NODES / 256, 256>>>();
    place_kernel<<<N_EDGES / 256, 256>>>(e_row, e_col);

    // temporal conv stack (FFMA2 co-pair packed)
    {
        dim3 g1(T2 / 256, BATCH);
        conv1_pool_kernel<<<g1, 256>>>(x, conv1_w, conv1_b);
        dim3 g2(T4 / 128, BATCH);
        conv2_pool_kernel<<<g2, 256>>>(conv2_w, conv2_b);
    }

    // GCN layer 1: aggregate 32-dim (fp16 payload), then matmul (+bias, relu)
    gather32_kernel<<<N_NODES / 8, 256>>>();
    xw_kernel<32, 1><<<N_NODES / 256, 256>>>(gcn1_w, gcn1_b);

    // GCN layer 2: matmul (dis-scaled, fp16 out), then aggregate 64-dim
    xw_kernel<64, 2><<<N_NODES / 256, 256>>>(gcn2_w, gcn2_b);
    gather64_kernel<<<N_NODES / 8, 256>>>(gcn2_b);

    // mean pool + classifier
    pool_cls_kernel<<<BATCH, 256>>>(cls_w, cls_b, out);
}

// round 6
// speedup vs baseline: 1.7260x; 1.0169x over previous
#include <cuda_runtime.h>
#include <cuda_bf16.h>
#include <cuda_fp16.h>

// ---------------- problem constants ----------------
#define BATCH   64
#define T_IN    8192
#define T2      4096        // after pool1
#define T4      2048        // after pool2
#define N_NODES 131072      // BATCH * T4
#define N_EDGES 2097152
#define HID     64
#define OUTC    10

typedef unsigned long long u64;

// ---------------- f32x2 packed helpers (Blackwell) ----------------
__device__ __forceinline__ u64 pk2(float lo, float hi) {
    u64 r; asm("mov.b64 %0, {%1, %2};" : "=l"(r) : "f"(lo), "f"(hi)); return r;
}
__device__ __forceinline__ void upk2(u64 v, float& lo, float& hi) {
    asm("mov.b64 {%0, %1}, %2;" : "=f"(lo), "=f"(hi) : "l"(v));
}
__device__ __forceinline__ void fma2(u64& acc, u64 a, u64 b) {
    asm("fma.rn.f32x2 %0, %1, %2, %3;" : "=l"(acc) : "l"(a), "l"(b), "l"(acc));
}

// ---------------- scratch (device globals, no allocation) ----------------
// NOTE: referenced ONLY inside device code (GB300 ATS silently reads the host
// shadow if passed as host-side kernel args).
__device__ __half2 g_feat_h[N_NODES * 16];       // conv2 out * dis, fp16, node-major
__device__ float   g_z[N_NODES * 32];            // aggregated 32-dim features (fp32)
__device__ __half2 g_y_h[N_NODES * 32];          // dis * (g1 @ W2), fp16
__device__ float   g_g1[N_NODES * 64];           // gcn1 output (fp32)
__device__ float   g_g2[N_NODES * 64];           // gcn2 output (fp32)
__device__ float   g_dis[N_NODES];
__device__ int     g_cnt[N_NODES];
__device__ int     g_off[N_NODES + 1];
__device__ int     g_cur[N_NODES];
__device__ int     g_srcs[N_EDGES];
__device__ int     g_bsum[128];

// ---------------- fused conv1+conv2+pools+dis-scale -> fp16 node features -----
// grid (T4/128, BATCH) x 256 threads. Dynamic smem (~75 KB):
//   sx  [16][528] : x tile, 524 valid (x0 = 512*tile - 6)
//   sh1 [16][264] : conv1 pooled tile, 260 valid (q0 = 256*tile - 2)
//   sw1 [8*16*5] u64, sw2 [16*16*5] u64 : co-pair packed weights
//   so  [128*17] half2 : transpose staging
#define SX_W   528
#define SX_V   524
#define SH1_W  264
#define SH1_V  260
#define SM_FLOATS (16*SX_W + 16*SH1_W + 16 + 32)
#define SM_BYTES  (SM_FLOATS*4 + (640+1280)*8 + 128*17*4)

__global__ void conv_fused_kernel(const float* __restrict__ x,
                                  const float* __restrict__ w1,
                                  const float* __restrict__ b1,
                                  const float* __restrict__ w2,
                                  const float* __restrict__ b2) {
    extern __shared__ float sm[];
    float*   sx  = sm;                       // [16][SX_W]
    float*   sh1 = sm + 16 * SX_W;           // [16][SH1_W]
    float*   sb1 = sh1 + 16 * SH1_W;         // [16]
    float*   sb2 = sb1 + 16;                 // [32]
    u64*     sw1 = (u64*)(sb2 + 32);         // [640]
    u64*     sw2 = sw1 + 640;                // [1280]
    __half2* so  = (__half2*)(sw2 + 1280);   // [128*17]

    const int tile = blockIdx.x, bb = blockIdx.y, tid = threadIdx.x;

    // ---- loads ----
    const int x0 = tile * 512 - 6;
    for (int i = tid; i < 16 * SX_V; i += 256) {
        int ci = i / SX_V, j = i - ci * SX_V;
        int t = x0 + j;
        sx[ci * SX_W + j] = (t >= 0 && t < T_IN) ? x[(bb * 16 + ci) * T_IN + t] : 0.f;
    }
    for (int i = tid; i < 640; i += 256) {
        int cp = i / 80, r = i - cp * 80;
        sw1[i] = pk2(w1[(2 * cp) * 80 + r], w1[(2 * cp + 1) * 80 + r]);
    }
    for (int i = tid; i < 1280; i += 256) {
        int cp = i / 80, r = i - cp * 80;
        sw2[i] = pk2(w2[(2 * cp) * 80 + r], w2[(2 * cp + 1) * 80 + r]);
    }
    if (tid < 16) sb1[tid] = b1[tid];
    else if (tid < 48) sb2[tid - 16] = b2[tid - 16];
    __syncthreads();

    // ---- phase 1: conv1 + relu + pool over the 260-wide halo tile ----
    const int q0 = tile * 256 - 2;
    for (int j = tid; j < SH1_V; j += 256) {
        const int q = q0 + j;
        if (q < 0 || q >= T2) {
#pragma unroll
            for (int co = 0; co < 16; co++) sh1[co * SH1_W + j] = 0.f;
            continue;
        }
        const int px = 2 * j;
        u64 a0[8], a1[8];
#pragma unroll
        for (int cp = 0; cp < 8; cp++) { a0[cp] = 0ull; a1[cp] = 0ull; }
#pragma unroll
        for (int ci = 0; ci < 16; ci++) {
            const float* sxp = &sx[ci * SX_W + px];
            float v0 = sxp[0], v1 = sxp[1], v2 = sxp[2];
            float v3 = sxp[3], v4 = sxp[4], v5 = sxp[5];
            u64 x0p = pk2(v0, v0), x1p = pk2(v1, v1), x2p = pk2(v2, v2);
            u64 x3p = pk2(v3, v3), x4p = pk2(v4, v4), x5p = pk2(v5, v5);
#pragma unroll
            for (int cp = 0; cp < 8; cp++) {
                const u64* wp = &sw1[(cp * 16 + ci) * 5];
                u64 w0 = wp[0], w1v = wp[1], w2v = wp[2], w3 = wp[3], w4 = wp[4];
                fma2(a0[cp], w0, x0p);  fma2(a1[cp], w0, x1p);
                fma2(a0[cp], w1v, x1p); fma2(a1[cp], w1v, x2p);
                fma2(a0[cp], w2v, x2p); fma2(a1[cp], w2v, x3p);
                fma2(a0[cp], w3, x3p);  fma2(a1[cp], w3, x4p);
                fma2(a0[cp], w4, x4p);  fma2(a1[cp], w4, x5p);
            }
        }
#pragma unroll
        for (int cp = 0; cp < 8; cp++) {
            float e0, o0, e1, o1;
            upk2(a0[cp], e0, o0);
            upk2(a1[cp], e1, o1);
            sh1[(2 * cp) * SH1_W + j]     = fmaxf(fmaxf(e0, e1) + sb1[2 * cp], 0.f);
            sh1[(2 * cp + 1) * SH1_W + j] = fmaxf(fmaxf(o0, o1) + sb1[2 * cp + 1], 0.f);
        }
    }
    __syncthreads();

    // ---- phase 2: conv2 + relu + pool + dis scale, fp16 transpose write ----
    const int tp  = tid & 127;
    const int cob = tid >> 7;
    const int p0  = 2 * tp;

    u64 acc0[8], acc1[8];
#pragma unroll
    for (int q = 0; q < 8; q++) { acc0[q] = 0ull; acc1[q] = 0ull; }

#pragma unroll
    for (int ci = 0; ci < 16; ci++) {
        const float* shp = &sh1[ci * SH1_W + p0];
        float v0 = shp[0], v1 = shp[1], v2 = shp[2];
        float v3 = shp[3], v4 = shp[4], v5 = shp[5];
        u64 x0p = pk2(v0, v0), x1p = pk2(v1, v1), x2p = pk2(v2, v2);
        u64 x3p = pk2(v3, v3), x4p = pk2(v4, v4), x5p = pk2(v5, v5);
#pragma unroll
        for (int q = 0; q < 8; q++) {
            const u64* wp = &sw2[((cob * 8 + q) * 16 + ci) * 5];
            u64 w0 = wp[0], w1v = wp[1], w2v = wp[2], w3 = wp[3], w4 = wp[4];
            fma2(acc0[q], w0, x0p);  fma2(acc1[q], w0, x1p);
            fma2(acc0[q], w1v, x1p); fma2(acc1[q], w1v, x2p);
            fma2(acc0[q], w2v, x2p); fma2(acc1[q], w2v, x3p);
            fma2(acc0[q], w3, x3p);  fma2(acc1[q], w3, x4p);
            fma2(acc0[q], w4, x4p);  fma2(acc1[q], w4, x5p);
        }
    }

    const int node_base = bb * T4 + tile * 128;
    const float d = __ldg(&g_dis[node_base + tp]);
#pragma unroll
    for (int q = 0; q < 8; q++) {
        int cp = cob * 8 + q;
        float e0, o0, e1, o1;
        upk2(acc0[q], e0, o0);
        upk2(acc1[q], e1, o1);
        float re = fmaxf(fmaxf(e0, e1) + sb2[2 * cp], 0.f) * d;
        float ro = fmaxf(fmaxf(o0, o1) + sb2[2 * cp + 1], 0.f) * d;
        so[tp * 17 + cp] = __floats2half2_rn(re, ro);
    }
    __syncthreads();

    for (int i = tid; i < 128 * 16; i += 256) {
        int lp = i >> 4, c = i & 15;
        g_feat_h[(node_base + lp) * 16 + c] = so[lp * 17 + c];
    }
}

// ---------------- CSR build ----------------
__global__ void zero_cnt_kernel() {
    int i = blockIdx.x * blockDim.x + threadIdx.x;
    if (i < N_NODES) g_cnt[i] = 0;
}

__global__ void hist_kernel(const int* __restrict__ col) {
    int e = blockIdx.x * blockDim.x + threadIdx.x;
    if (e < N_EDGES) atomicAdd(&g_cnt[col[e]], 1);
}

// scan1 also produces g_dis (counts already in registers)
__global__ void scan1_kernel() {
    __shared__ int ss[256];
    const int tid = threadIdx.x;
    const int base = blockIdx.x * 1024 + tid * 4;
    int v0 = g_cnt[base], v1 = g_cnt[base + 1], v2 = g_cnt[base + 2], v3 = g_cnt[base + 3];
    g_dis[base]     = rsqrtf((float)(v0 + 1));
    g_dis[base + 1] = rsqrtf((float)(v1 + 1));
    g_dis[base + 2] = rsqrtf((float)(v2 + 1));
    g_dis[base + 3] = rsqrtf((float)(v3 + 1));
    int tsum = v0 + v1 + v2 + v3;
    ss[tid] = tsum;
    __syncthreads();
    for (int d = 1; d < 256; d <<= 1) {
        int t = (tid >= d) ? ss[tid - d] : 0;
        __syncthreads();
        ss[tid] += t;
        __syncthreads();
    }
    int excl = ss[tid] - tsum;
    g_off[base]     = excl;
    g_off[base + 1] = excl + v0;
    g_off[base + 2] = excl + v0 + v1;
    g_off[base + 3] = excl + v0 + v1 + v2;
    if (tid == 255) g_bsum[blockIdx.x] = ss[255];
}

__global__ void scan2_kernel() {
    __shared__ int ss[128];
    const int tid = threadIdx.x;
    int v = g_bsum[tid];
    ss[tid] = v;
    __syncthreads();
    for (int d = 1; d < 128; d <<= 1) {
        int t = (tid >= d) ? ss[tid - d] : 0;
        __syncthreads();
        ss[tid] += t;
        __syncthreads();
    }
    g_bsum[tid] = ss[tid] - v;
}

__global__ void scan3_kernel() {
    int i = blockIdx.x * blockDim.x + threadIdx.x;
    if (i < N_NODES) {
        int o = g_off[i] + g_bsum[i >> 10];
        g_off[i] = o;
        g_cur[i] = o;
        if (i == 0) g_off[N_NODES] = N_EDGES;
    }
}

__global__ void place_kernel(const int* __restrict__ row, const int* __restrict__ col) {
    int e = blockIdx.x * blockDim.x + threadIdx.x;
    if (e < N_EDGES) {
        int c = col[e];
        int p = atomicAdd(&g_cur[c], 1);
        g_srcs[p] = row[e];
    }
}

// ---------------- gather32 (fp16): z[i] = dis_i * (feat~[i] + sum feat~[j]) ----
__global__ void gather32_kernel() {
    const int gw = (blockIdx.x * 256 + threadIdx.x) >> 5;
    const int lane = threadIdx.x & 31;
    const int hw = lane >> 4, c = lane & 15;
    const __half2* __restrict__ y = g_feat_h;

    float ax = 0.f, ay = 0.f;
    int p = g_off[gw];
    const int e = g_off[gw + 1];
    for (; p + 8 <= e; p += 8) {
        int j0 = __ldg(&g_srcs[p + 0 + hw]);
        int j1 = __ldg(&g_srcs[p + 2 + hw]);
        int j2 = __ldg(&g_srcs[p + 4 + hw]);
        int j3 = __ldg(&g_srcs[p + 6 + hw]);
        float2 v0 = __half22float2(__ldg(&y[j0 * 16 + c]));
        float2 v1 = __half22float2(__ldg(&y[j1 * 16 + c]));
        float2 v2 = __half22float2(__ldg(&y[j2 * 16 + c]));
        float2 v3 = __half22float2(__ldg(&y[j3 * 16 + c]));
        ax += (v0.x + v1.x) + (v2.x + v3.x);
        ay += (v0.y + v1.y) + (v2.y + v3.y);
    }
    for (; p + 2 <= e; p += 2) {
        int j = __ldg(&g_srcs[p + hw]);
        float2 v = __half22float2(__ldg(&y[j * 16 + c]));
        ax += v.x; ay += v.y;
    }
    if (p < e && hw == 0) {
        int j = __ldg(&g_srcs[p]);
        float2 v = __half22float2(__ldg(&y[j * 16 + c]));
        ax += v.x; ay += v.y;
    }
    ax += __shfl_xor_sync(0xFFFFFFFFu, ax, 16);
    ay += __shfl_xor_sync(0xFFFFFFFFu, ay, 16);
    if (lane < 16) {
        float2 self = __half22float2(__ldg(&y[gw * 16 + c]));
        const float d = g_dis[gw];
        float2 r;
        r.x = (self.x + ax) * d;
        r.y = (self.y + ay) * d;
        ((float2*)g_z)[gw * 16 + c] = r;
    }
}

// ---------------- xw: register-blocked GEMV with f32x2 ----------------
// MODE 1: g_g1 = relu(g_z @ W + bias)        (IN = 32, fp32 out)
// MODE 2: g_y_h = dis * (g_g1 @ W)  (fp16)   (IN = 64)
template <int IN, int MODE>
__global__ void xw_kernel(const float* __restrict__ W, const float* __restrict__ bias) {
    __shared__ __align__(16) u64 sW2[IN * 32];
    const int tid = threadIdx.x;
    const float2* Wf2 = (const float2*)W;
    for (int i = tid; i < IN * 32; i += 256) {
        float2 wv = Wf2[i];
        sW2[i] = pk2(wv.x, wv.y);
    }
    __syncthreads();

    const int lane = tid & 31, wp = tid >> 5;
    const int n = blockIdx.x * 256 + wp * 32 + lane;
    const float* __restrict__ f = (MODE == 1) ? g_z : g_g1;

    u64 acc[32];
#pragma unroll
    for (int j = 0; j < 32; j++) acc[j] = 0ull;

    const float4* fv = (const float4*)(f + (size_t)n * IN);
#pragma unroll
    for (int kc = 0; kc < IN / 4; kc++) {
        float4 xv = fv[kc];
        float xs0 = xv.x, xs1 = xv.y, xs2 = xv.z, xs3 = xv.w;
#pragma unroll
        for (int kk = 0; kk < 4; kk++) {
            float xk = (kk == 0) ? xs0 : (kk == 1) ? xs1 : (kk == 2) ? xs2 : xs3;
            u64 x2 = pk2(xk, xk);
            const ulonglong2* wrow = (const ulonglong2*)&sW2[(kc * 4 + kk) * 32];
#pragma unroll
            for (int j = 0; j < 16; j++) {
                ulonglong2 wv = wrow[j];
                fma2(acc[2 * j],     x2, wv.x);
                fma2(acc[2 * j + 1], x2, wv.y);
            }
        }
    }

    if (MODE == 1) {
        float* o = g_g1 + (size_t)n * 64;
#pragma unroll
        for (int j = 0; j < 16; j++) {
            float l0, h0, l1, h1;
            upk2(acc[2 * j], l0, h0);
            upk2(acc[2 * j + 1], l1, h1);
            float4 r;
            r.x = fmaxf(l0 + __ldg(&bias[4 * j + 0]), 0.f);
            r.y = fmaxf(h0 + __ldg(&bias[4 * j + 1]), 0.f);
            r.z = fmaxf(l1 + __ldg(&bias[4 * j + 2]), 0.f);
            r.w = fmaxf(h1 + __ldg(&bias[4 * j + 3]), 0.f);
            ((float4*)o)[j] = r;
        }
    } else {
        const float di = g_dis[n];
        __half2* o = g_y_h + (size_t)n * 32;
#pragma unroll
        for (int q = 0; q < 8; q++) {
            float l0, h0, l1, h1, l2, h2, l3, h3;
            upk2(acc[4 * q + 0], l0, h0);
            upk2(acc[4 * q + 1], l1, h1);
            upk2(acc[4 * q + 2], l2, h2);
            upk2(acc[4 * q + 3], l3, h3);
            __half2 a = __floats2half2_rn(l0 * di, h0 * di);
            __half2 b = __floats2half2_rn(l1 * di, h1 * di);
            __half2 cc = __floats2half2_rn(l2 * di, h2 * di);
            __half2 dd = __floats2half2_rn(l3 * di, h3 * di);
            uint4 pack;
            pack.x = *(unsigned*)&a;  pack.y = *(unsigned*)&b;
            pack.z = *(unsigned*)&cc; pack.w = *(unsigned*)&dd;
            ((uint4*)o)[q] = pack;
        }
    }
}

// ---------------- gather64 (fp16): g2[i] = relu(dis_i*(y_i + sum y_j) + bias) ----
__global__ void gather64_kernel(const float* __restrict__ bias) {
    const __half2* __restrict__ y = g_y_h;
    const int gw = (blockIdx.x * 256 + threadIdx.x) >> 5;
    const int lane = threadIdx.x & 31;

    float2 a = __half22float2(__ldg(&y[gw * 32 + lane]));
    int p = g_off[gw];
    const int e = g_off[gw + 1];
    for (; p + 8 <= e; p += 8) {
        int j0 = __ldg(&g_srcs[p + 0]), j1 = __ldg(&g_srcs[p + 1]);
        int j2 = __ldg(&g_srcs[p + 2]), j3 = __ldg(&g_srcs[p + 3]);
        int j4 = __ldg(&g_srcs[p + 4]), j5 = __ldg(&g_srcs[p + 5]);
        int j6 = __ldg(&g_srcs[p + 6]), j7 = __ldg(&g_srcs[p + 7]);
        float2 v0 = __half22float2(__ldg(&y[j0 * 32 + lane]));
        float2 v1 = __half22float2(__ldg(&y[j1 * 32 + lane]));
        float2 v2 = __half22float2(__ldg(&y[j2 * 32 + lane]));
        float2 v3 = __half22float2(__ldg(&y[j3 * 32 + lane]));
        float2 v4 = __half22float2(__ldg(&y[j4 * 32 + lane]));
        float2 v5 = __half22float2(__ldg(&y[j5 * 32 + lane]));
        float2 v6 = __half22float2(__ldg(&y[j6 * 32 + lane]));
        float2 v7 = __half22float2(__ldg(&y[j7 * 32 + lane]));
        a.x += ((v0.x + v1.x) + (v2.x + v3.x)) + ((v4.x + v5.x) + (v6.x + v7.x));
        a.y += ((v0.y + v1.y) + (v2.y + v3.y)) + ((v4.y + v5.y) + (v6.y + v7.y));
    }
    for (; p < e; p++) {
        int j = __ldg(&g_srcs[p]);
        float2 v = __half22float2(__ldg(&y[j * 32 + lane]));
        a.x += v.x; a.y += v.y;
    }
    const float d = g_dis[gw];
    float2 bb = ((const float2*)bias)[lane];
    float2 r;
    r.x = fmaxf(fmaf(d, a.x, bb.x), 0.f);
    r.y = fmaxf(fmaf(d, a.y, bb.y), 0.f);
    ((float2*)g_g2)[gw * 32 + lane] = r;
}

// ---------------- mean pool + classifier ----------------
__global__ void pool_cls_kernel(const float* __restrict__ clsw,
                                const float* __restrict__ clsb,
                                float* __restrict__ out) {
    __shared__ float sp[256];
    __shared__ float pooled[64];
    const int b = blockIdx.x, tid = threadIdx.x;
    const int c = tid & 63, q = tid >> 6;
    float s = 0.f;
    for (int n = q; n < T4; n += 4)
        s += g_g2[((size_t)b * T4 + n) * 64 + c];
    sp[tid] = s;
    __syncthreads();
    if (tid < 64)
        pooled[tid] = (sp[tid] + sp[tid + 64] + sp[tid + 128] + sp[tid + 192]) * (1.f / (float)T4);
    __syncthreads();
    if (tid < OUTC) {
        float acc = clsb[tid];
#pragma unroll
        for (int cc = 0; cc < 64; cc++) acc += pooled[cc] * clsw[cc * OUTC + tid];
        out[b * OUTC + tid] = acc;
    }
}

// ---------------- launch ----------------
extern "C" void kernel_launch(void* const* d_in, const int* in_sizes, int n_in,
                              void* d_out, int out_size) {
    const float* x       = nullptr;
    const int*   ei      = nullptr;
    const float* conv1_w = nullptr; const float* conv1_b = nullptr;
    const float* conv2_w = nullptr; const float* conv2_b = nullptr;
    const float* gcn1_w  = nullptr; const float* gcn1_b  = nullptr;
    const float* gcn2_w  = nullptr; const float* gcn2_b  = nullptr;
    const float* cls_w   = nullptr; const float* cls_b   = nullptr;

    for (int i = 0; i < n_in; i++) {
        switch (in_sizes[i]) {
            case BATCH * 16 * T_IN:   x       = (const float*)d_in[i]; break;
            case 2 * N_EDGES:         ei      = (const int*)  d_in[i]; break;
            case 16 * 16 * 5:         conv1_w = (const float*)d_in[i]; break;
            case 16:                  conv1_b = (const float*)d_in[i]; break;
            case 32 * 16 * 5:         conv2_w = (const float*)d_in[i]; break;
            case 32:                  conv2_b = (const float*)d_in[i]; break;
            case 32 * HID:            gcn1_w  = (const float*)d_in[i]; break;
            case HID * HID:           gcn2_w  = (const float*)d_in[i]; break;
            case HID * OUTC:          cls_w   = (const float*)d_in[i]; break;
            case OUTC:                cls_b   = (const float*)d_in[i]; break;
            case HID:
                if (!gcn1_b) gcn1_b = (const float*)d_in[i];
                else         gcn2_b = (const float*)d_in[i];
                break;
            default: break;
        }
    }
    if (!x || !ei || !conv1_w || !conv2_w || !gcn1_w || !gcn2_w || !cls_w) {
        x       = (const float*)d_in[0];  ei      = (const int*)  d_in[1];
        conv1_w = (const float*)d_in[2];  conv1_b = (const float*)d_in[3];
        conv2_w = (const float*)d_in[4];  conv2_b = (const float*)d_in[5];
        gcn1_w  = (const float*)d_in[6];  gcn1_b  = (const float*)d_in[7];
        gcn2_w  = (const float*)d_in[8];  gcn2_b  = (const float*)d_in[9];
        cls_w   = (const float*)d_in[10]; cls_b   = (const float*)d_in[11];
    }

    float* out = (float*)d_out;
    const int* e_row = ei;
    const int* e_col = ei + N_EDGES;

    static bool attr_set = false;
    // idempotent; safe to call every time (not a stream op, not an allocation)
    cudaFuncSetAttribute(conv_fused_kernel,
                         cudaFuncAttributeMaxDynamicSharedMemorySize, SM_BYTES);
    (void)attr_set;

    // CSR build; conv_fused placed at launch index 3 (profiler slot)
    zero_cnt_kernel<<<N_NODES / 256, 256>>>();
    hist_kernel<<<N_EDGES / 256, 256>>>(e_col);
    scan1_kernel<<<128, 256>>>();                 // also computes g_dis
    {
        dim3 gc(T4 / 128, BATCH);
        conv_fused_kernel<<<gc, 256, SM_BYTES>>>(x, conv1_w, conv1_b, conv2_w, conv2_b);
    }
    scan2_kernel<<<1, 128>>>();
    scan3_kernel<<<N_NODES / 256, 256>>>();
    place_kernel<<<N_EDGES / 256, 256>>>(e_row, e_col);

    // GCN layer 1: aggregate 32-dim (fp16 payload), then matmul (+bias, relu)
    gather32_kernel<<<N_NODES / 8, 256>>>();
    xw_kernel<32, 1><<<N_NODES / 256, 256>>>(gcn1_w, gcn1_b);

    // GCN layer 2: matmul (dis-scaled, fp16 out), then aggregate 64-dim
    xw_kernel<64, 2><<<N_NODES / 256, 256>>>(gcn2_w, gcn2_b);
    gather64_kernel<<<N_NODES / 8, 256>>>(gcn2_b);

    // mean pool + classifier
    pool_cls_kernel<<<BATCH, 256>>>(cls_w, cls_b, out);
}

// round 7
// speedup vs baseline: 1.7947x; 1.0398x over previous
#include <cuda_runtime.h>
#include <cuda_bf16.h>
#include <cuda_fp16.h>

// ---------------- problem constants ----------------
#define BATCH   64
#define T_IN    8192
#define T2      4096        // after pool1
#define T4      2048        // after pool2
#define N_NODES 131072      // BATCH * T4
#define N_EDGES 2097152
#define HID     64
#define OUTC    10

typedef unsigned long long u64;

// ---------------- f32x2 packed helpers (Blackwell) ----------------
__device__ __forceinline__ u64 pk2(float lo, float hi) {
    u64 r; asm("mov.b64 %0, {%1, %2};" : "=l"(r) : "f"(lo), "f"(hi)); return r;
}
__device__ __forceinline__ void upk2(u64 v, float& lo, float& hi) {
    asm("mov.b64 {%0, %1}, %2;" : "=f"(lo), "=f"(hi) : "l"(v));
}
__device__ __forceinline__ void fma2(u64& acc, u64 a, u64 b) {
    asm("fma.rn.f32x2 %0, %1, %2, %3;" : "=l"(acc) : "l"(a), "l"(b), "l"(acc));
}

// ---------------- scratch (device globals, no allocation) ----------------
// NOTE: referenced ONLY inside device code (GB300 ATS silently reads the host
// shadow if passed as host-side kernel args).
__device__ __half2 g_feat_h[N_NODES * 16];       // conv2 out * dis, fp16, node-major
__device__ float   g_z[N_NODES * 32];            // aggregated 32-dim features (fp32)
__device__ __half2 g_y_h[N_NODES * 32];          // dis * (relu(z@W1+b1) @ W2), fp16
__device__ float   g_g2[N_NODES * 64];           // gcn2 output (fp32)
__device__ float   g_dis[N_NODES];
__device__ int     g_cnt[N_NODES];
__device__ int     g_off[N_NODES + 1];
__device__ int     g_cur[N_NODES];
__device__ int     g_srcs[N_EDGES];
__device__ int     g_bsum[128];

// ---------------- fused conv1+conv2+pools+dis-scale -> fp16 node features -----
// grid (T4/128, BATCH) x 256 threads. Weights padded to stride 6 u64 so each
// (cp,ci) quintet loads as LDS.128 x2 + LDS.64; x windows load as float2 x3.
#define SX_W   528
#define SX_V   524
#define SH1_W  264
#define SH1_V  260
#define SW1_N  (8 * 16 * 6)
#define SW2_N  (16 * 16 * 6)
#define SM_FLOATS (16*SX_W + 16*SH1_W + 16 + 32)
#define SM_BYTES  (SM_FLOATS*4 + (SW1_N + SW2_N)*8 + 128*17*4)

__global__ void conv_fused_kernel(const float* __restrict__ x,
                                  const float* __restrict__ w1,
                                  const float* __restrict__ b1,
                                  const float* __restrict__ w2,
                                  const float* __restrict__ b2) {
    extern __shared__ float sm[];
    float*   sx  = sm;                       // [16][SX_W]
    float*   sh1 = sm + 16 * SX_W;           // [16][SH1_W]
    float*   sb1 = sh1 + 16 * SH1_W;         // [16]
    float*   sb2 = sb1 + 16;                 // [32]
    u64*     sw1 = (u64*)(sb2 + 32);         // [SW1_N] stride-6 padded
    u64*     sw2 = sw1 + SW1_N;              // [SW2_N]
    __half2* so  = (__half2*)(sw2 + SW2_N);  // [128*17]

    const int tile = blockIdx.x, bb = blockIdx.y, tid = threadIdx.x;

    // ---- loads ----
    const int x0 = tile * 512 - 6;
    for (int i = tid; i < 16 * SX_V; i += 256) {
        int ci = i / SX_V, j = i - ci * SX_V;
        int t = x0 + j;
        sx[ci * SX_W + j] = (t >= 0 && t < T_IN) ? x[(bb * 16 + ci) * T_IN + t] : 0.f;
    }
    for (int i = tid; i < 8 * 16 * 5; i += 256) {
        int cp = i / 80, r = i - cp * 80;       // r = ci*5 + k
        int ci = r / 5, k = r - ci * 5;
        sw1[(cp * 16 + ci) * 6 + k] = pk2(w1[(2 * cp) * 80 + r], w1[(2 * cp + 1) * 80 + r]);
    }
    for (int i = tid; i < 16 * 16 * 5; i += 256) {
        int cp = i / 80, r = i - cp * 80;
        int ci = r / 5, k = r - ci * 5;
        sw2[(cp * 16 + ci) * 6 + k] = pk2(w2[(2 * cp) * 80 + r], w2[(2 * cp + 1) * 80 + r]);
    }
    if (tid < 16) sb1[tid] = b1[tid];
    else if (tid < 48) sb2[tid - 16] = b2[tid - 16];
    __syncthreads();

    // ---- phase 1: conv1 + relu + pool over the 260-wide halo tile ----
    const int q0 = tile * 256 - 2;
    for (int j = tid; j < SH1_V; j += 256) {
        const int q = q0 + j;
        if (q < 0 || q >= T2) {
#pragma unroll
            for (int co = 0; co < 16; co++) sh1[co * SH1_W + j] = 0.f;
            continue;
        }
        const int px = 2 * j;
        u64 a0[8], a1[8];
#pragma unroll
        for (int cp = 0; cp < 8; cp++) { a0[cp] = 0ull; a1[cp] = 0ull; }
#pragma unroll
        for (int ci = 0; ci < 16; ci++) {
            const float2* sxp = (const float2*)&sx[ci * SX_W + px];
            float2 v01 = sxp[0], v23 = sxp[1], v45 = sxp[2];
            u64 x0p = pk2(v01.x, v01.x), x1p = pk2(v01.y, v01.y), x2p = pk2(v23.x, v23.x);
            u64 x3p = pk2(v23.y, v23.y), x4p = pk2(v45.x, v45.x), x5p = pk2(v45.y, v45.y);
#pragma unroll
            for (int cp = 0; cp < 8; cp++) {
                const u64* wp = &sw1[(cp * 16 + ci) * 6];
                ulonglong2 wA = *(const ulonglong2*)wp;        // w0, w1
                ulonglong2 wB = *(const ulonglong2*)(wp + 2);  // w2, w3
                u64 w4 = wp[4];
                fma2(a0[cp], wA.x, x0p); fma2(a1[cp], wA.x, x1p);
                fma2(a0[cp], wA.y, x1p); fma2(a1[cp], wA.y, x2p);
                fma2(a0[cp], wB.x, x2p); fma2(a1[cp], wB.x, x3p);
                fma2(a0[cp], wB.y, x3p); fma2(a1[cp], wB.y, x4p);
                fma2(a0[cp], w4,   x4p); fma2(a1[cp], w4,   x5p);
            }
        }
#pragma unroll
        for (int cp = 0; cp < 8; cp++) {
            float e0, o0, e1, o1;
            upk2(a0[cp], e0, o0);
            upk2(a1[cp], e1, o1);
            sh1[(2 * cp) * SH1_W + j]     = fmaxf(fmaxf(e0, e1) + sb1[2 * cp], 0.f);
            sh1[(2 * cp + 1) * SH1_W + j] = fmaxf(fmaxf(o0, o1) + sb1[2 * cp + 1], 0.f);
        }
    }
    __syncthreads();

    // ---- phase 2: conv2 + relu + pool + dis scale, fp16 transpose write ----
    const int tp  = tid & 127;
    const int cob = tid >> 7;
    const int p0  = 2 * tp;

    u64 acc0[8], acc1[8];
#pragma unroll
    for (int q = 0; q < 8; q++) { acc0[q] = 0ull; acc1[q] = 0ull; }

#pragma unroll
    for (int ci = 0; ci < 16; ci++) {
        const float2* shp = (const float2*)&sh1[ci * SH1_W + p0];
        float2 v01 = shp[0], v23 = shp[1], v45 = shp[2];
        u64 x0p = pk2(v01.x, v01.x), x1p = pk2(v01.y, v01.y), x2p = pk2(v23.x, v23.x);
        u64 x3p = pk2(v23.y, v23.y), x4p = pk2(v45.x, v45.x), x5p = pk2(v45.y, v45.y);
#pragma unroll
        for (int q = 0; q < 8; q++) {
            const u64* wp = &sw2[((cob * 8 + q) * 16 + ci) * 6];
            ulonglong2 wA = *(const ulonglong2*)wp;
            ulonglong2 wB = *(const ulonglong2*)(wp + 2);
            u64 w4 = wp[4];
            fma2(acc0[q], wA.x, x0p); fma2(acc1[q], wA.x, x1p);
            fma2(acc0[q], wA.y, x1p); fma2(acc1[q], wA.y, x2p);
            fma2(acc0[q], wB.x, x2p); fma2(acc1[q], wB.x, x3p);
            fma2(acc0[q], wB.y, x3p); fma2(acc1[q], wB.y, x4p);
            fma2(acc0[q], w4,   x4p); fma2(acc1[q], w4,   x5p);
        }
    }

    const int node_base = bb * T4 + tile * 128;
    const float d = __ldg(&g_dis[node_base + tp]);
#pragma unroll
    for (int q = 0; q < 8; q++) {
        int cp = cob * 8 + q;
        float e0, o0, e1, o1;
        upk2(acc0[q], e0, o0);
        upk2(acc1[q], e1, o1);
        float re = fmaxf(fmaxf(e0, e1) + sb2[2 * cp], 0.f) * d;
        float ro = fmaxf(fmaxf(o0, o1) + sb2[2 * cp + 1], 0.f) * d;
        so[tp * 17 + cp] = __floats2half2_rn(re, ro);
    }
    __syncthreads();

    for (int i = tid; i < 128 * 16; i += 256) {
        int lp = i >> 4, c = i & 15;
        g_feat_h[(node_base + lp) * 16 + c] = so[lp * 17 + c];
    }
}

// ---------------- CSR build ----------------
__global__ void zero_cnt_kernel() {
    int i = blockIdx.x * blockDim.x + threadIdx.x;
    if (i < N_NODES) g_cnt[i] = 0;
}

__global__ void hist_kernel(const int* __restrict__ col) {
    int e = blockIdx.x * blockDim.x + threadIdx.x;
    if (e < N_EDGES) atomicAdd(&g_cnt[col[e]], 1);
}

// scan1 also produces g_dis (counts already in registers)
__global__ void scan1_kernel() {
    __shared__ int ss[256];
    const int tid = threadIdx.x;
    const int base = blockIdx.x * 1024 + tid * 4;
    int v0 = g_cnt[base], v1 = g_cnt[base + 1], v2 = g_cnt[base + 2], v3 = g_cnt[base + 3];
    g_dis[base]     = rsqrtf((float)(v0 + 1));
    g_dis[base + 1] = rsqrtf((float)(v1 + 1));
    g_dis[base + 2] = rsqrtf((float)(v2 + 1));
    g_dis[base + 3] = rsqrtf((float)(v3 + 1));
    int tsum = v0 + v1 + v2 + v3;
    ss[tid] = tsum;
    __syncthreads();
    for (int d = 1; d < 256; d <<= 1) {
        int t = (tid >= d) ? ss[tid - d] : 0;
        __syncthreads();
        ss[tid] += t;
        __syncthreads();
    }
    int excl = ss[tid] - tsum;
    g_off[base]     = excl;
    g_off[base + 1] = excl + v0;
    g_off[base + 2] = excl + v0 + v1;
    g_off[base + 3] = excl + v0 + v1 + v2;
    if (tid == 255) g_bsum[blockIdx.x] = ss[255];
}

__global__ void scan2_kernel() {
    __shared__ int ss[128];
    const int tid = threadIdx.x;
    int v = g_bsum[tid];
    ss[tid] = v;
    __syncthreads();
    for (int d = 1; d < 128; d <<= 1) {
        int t = (tid >= d) ? ss[tid - d] : 0;
        __syncthreads();
        ss[tid] += t;
        __syncthreads();
    }
    g_bsum[tid] = ss[tid] - v;
}

__global__ void scan3_kernel() {
    int i = blockIdx.x * blockDim.x + threadIdx.x;
    if (i < N_NODES) {
        int o = g_off[i] + g_bsum[i >> 10];
        g_off[i] = o;
        g_cur[i] = o;
        if (i == 0) g_off[N_NODES] = N_EDGES;
    }
}

__global__ void place_kernel(const int* __restrict__ row, const int* __restrict__ col) {
    int e = blockIdx.x * blockDim.x + threadIdx.x;
    if (e < N_EDGES) {
        int c = col[e];
        int p = atomicAdd(&g_cur[c], 1);
        g_srcs[p] = row[e];
    }
}

// ---------------- gather32 (fp16): z[i] = dis_i * (feat~[i] + sum feat~[j]) ----
__global__ void gather32_kernel() {
    const int gw = (blockIdx.x * 256 + threadIdx.x) >> 5;
    const int lane = threadIdx.x & 31;
    const int hw = lane >> 4, c = lane & 15;
    const __half2* __restrict__ y = g_feat_h;

    float ax = 0.f, ay = 0.f;
    int p = g_off[gw];
    const int e = g_off[gw + 1];
    for (; p + 8 <= e; p += 8) {
        int j0 = __ldg(&g_srcs[p + 0 + hw]);
        int j1 = __ldg(&g_srcs[p + 2 + hw]);
        int j2 = __ldg(&g_srcs[p + 4 + hw]);
        int j3 = __ldg(&g_srcs[p + 6 + hw]);
        float2 v0 = __half22float2(__ldg(&y[j0 * 16 + c]));
        float2 v1 = __half22float2(__ldg(&y[j1 * 16 + c]));
        float2 v2 = __half22float2(__ldg(&y[j2 * 16 + c]));
        float2 v3 = __half22float2(__ldg(&y[j3 * 16 + c]));
        ax += (v0.x + v1.x) + (v2.x + v3.x);
        ay += (v0.y + v1.y) + (v2.y + v3.y);
    }
    for (; p + 2 <= e; p += 2) {
        int j = __ldg(&g_srcs[p + hw]);
        float2 v = __half22float2(__ldg(&y[j * 16 + c]));
        ax += v.x; ay += v.y;
    }
    if (p < e && hw == 0) {
        int j = __ldg(&g_srcs[p]);
        float2 v = __half22float2(__ldg(&y[j * 16 + c]));
        ax += v.x; ay += v.y;
    }
    ax += __shfl_xor_sync(0xFFFFFFFFu, ax, 16);
    ay += __shfl_xor_sync(0xFFFFFFFFu, ay, 16);
    if (lane < 16) {
        float2 self = __half22float2(__ldg(&y[gw * 16 + c]));
        const float d = g_dis[gw];
        float2 r;
        r.x = (self.x + ax) * d;
        r.y = (self.y + ay) * d;
        ((float2*)g_z)[gw * 16 + c] = r;
    }
}

// ---------------- fused GCN matmuls: y = dis * (relu(z@W1 + b1) @ W2), fp16 ----
// One thread per node; h never leaves registers.
__global__ void xw_fused_kernel(const float* __restrict__ W1,
                                const float* __restrict__ b1,
                                const float* __restrict__ W2) {
    __shared__ __align__(16) u64 sW1[32 * 32];   // [k][j] output-channel pairs
    __shared__ __align__(16) u64 sW2[64 * 32];
    __shared__ float sb1v[64];
    const int tid = threadIdx.x;
    for (int i = tid; i < 32 * 32; i += 256) {
        float2 wv = ((const float2*)W1)[i];
        sW1[i] = pk2(wv.x, wv.y);
    }
    for (int i = tid; i < 64 * 32; i += 256) {
        float2 wv = ((const float2*)W2)[i];
        sW2[i] = pk2(wv.x, wv.y);
    }
    if (tid < 64) sb1v[tid] = b1[tid];
    __syncthreads();

    const int n = blockIdx.x * 256 + tid;

    // stage 1: acc1 = z @ W1 (64 channels in 32 packed accumulators)
    u64 acc1[32];
#pragma unroll
    for (int j = 0; j < 32; j++) acc1[j] = 0ull;
    const float4* fv = (const float4*)(g_z + (size_t)n * 32);
#pragma unroll
    for (int kc = 0; kc < 8; kc++) {
        float4 xv = fv[kc];
#pragma unroll
        for (int kk = 0; kk < 4; kk++) {
            float xk = (kk == 0) ? xv.x : (kk == 1) ? xv.y : (kk == 2) ? xv.z : xv.w;
            u64 x2 = pk2(xk, xk);
            const ulonglong2* wrow = (const ulonglong2*)&sW1[(kc * 4 + kk) * 32];
#pragma unroll
            for (int j = 0; j < 16; j++) {
                ulonglong2 wv = wrow[j];
                fma2(acc1[2 * j],     x2, wv.x);
                fma2(acc1[2 * j + 1], x2, wv.y);
            }
        }
    }

    // stage 2: h_k = relu(acc1_k + b1_k) consumed immediately into acc2
    u64 acc2[32];
#pragma unroll
    for (int j = 0; j < 32; j++) acc2[j] = 0ull;
#pragma unroll
    for (int j = 0; j < 32; j++) {
        float l, h;
        upk2(acc1[j], l, h);
        l = fmaxf(l + sb1v[2 * j], 0.f);
        h = fmaxf(h + sb1v[2 * j + 1], 0.f);
        u64 xl = pk2(l, l), xh = pk2(h, h);
        const ulonglong2* r0 = (const ulonglong2*)&sW2[(2 * j) * 32];
        const ulonglong2* r1 = (const ulonglong2*)&sW2[(2 * j + 1) * 32];
#pragma unroll
        for (int m = 0; m < 16; m++) {
            ulonglong2 wa = r0[m];
            fma2(acc2[2 * m],     xl, wa.x);
            fma2(acc2[2 * m + 1], xl, wa.y);
            ulonglong2 wb = r1[m];
            fma2(acc2[2 * m],     xh, wb.x);
            fma2(acc2[2 * m + 1], xh, wb.y);
        }
    }

    const float di = g_dis[n];
    __half2* o = g_y_h + (size_t)n * 32;
#pragma unroll
    for (int q = 0; q < 8; q++) {
        float l0, h0, l1, h1, l2, h2, l3, h3;
        upk2(acc2[4 * q + 0], l0, h0);
        upk2(acc2[4 * q + 1], l1, h1);
        upk2(acc2[4 * q + 2], l2, h2);
        upk2(acc2[4 * q + 3], l3, h3);
        __half2 a = __floats2half2_rn(l0 * di, h0 * di);
        __half2 b = __floats2half2_rn(l1 * di, h1 * di);
        __half2 cc = __floats2half2_rn(l2 * di, h2 * di);
        __half2 dd = __floats2half2_rn(l3 * di, h3 * di);
        uint4 pack;
        pack.x = *(unsigned*)&a;  pack.y = *(unsigned*)&b;
        pack.z = *(unsigned*)&cc; pack.w = *(unsigned*)&dd;
        ((uint4*)o)[q] = pack;
    }
}

// ---------------- gather64 (fp16): g2[i] = relu(dis_i*(y_i + sum y_j) + bias) ----
__global__ void gather64_kernel(const float* __restrict__ bias) {
    const __half2* __restrict__ y = g_y_h;
    const int gw = (blockIdx.x * 256 + threadIdx.x) >> 5;
    const int lane = threadIdx.x & 31;

    float2 a = __half22float2(__ldg(&y[gw * 32 + lane]));
    int p = g_off[gw];
    const int e = g_off[gw + 1];
    for (; p + 8 <= e; p += 8) {
        int j0 = __ldg(&g_srcs[p + 0]), j1 = __ldg(&g_srcs[p + 1]);
        int j2 = __ldg(&g_srcs[p + 2]), j3 = __ldg(&g_srcs[p + 3]);
        int j4 = __ldg(&g_srcs[p + 4]), j5 = __ldg(&g_srcs[p + 5]);
        int j6 = __ldg(&g_srcs[p + 6]), j7 = __ldg(&g_srcs[p + 7]);
        float2 v0 = __half22float2(__ldg(&y[j0 * 32 + lane]));
        float2 v1 = __half22float2(__ldg(&y[j1 * 32 + lane]));
        float2 v2 = __half22float2(__ldg(&y[j2 * 32 + lane]));
        float2 v3 = __half22float2(__ldg(&y[j3 * 32 + lane]));
        float2 v4 = __half22float2(__ldg(&y[j4 * 32 + lane]));
        float2 v5 = __half22float2(__ldg(&y[j5 * 32 + lane]));
        float2 v6 = __half22float2(__ldg(&y[j6 * 32 + lane]));
        float2 v7 = __half22float2(__ldg(&y[j7 * 32 + lane]));
        a.x += ((v0.x + v1.x) + (v2.x + v3.x)) + ((v4.x + v5.x) + (v6.x + v7.x));
        a.y += ((v0.y + v1.y) + (v2.y + v3.y)) + ((v4.y + v5.y) + (v6.y + v7.y));
    }
    for (; p < e; p++) {
        int j = __ldg(&g_srcs[p]);
        float2 v = __half22float2(__ldg(&y[j * 32 + lane]));
        a.x += v.x; a.y += v.y;
    }
    const float d = g_dis[gw];
    float2 bb = ((const float2*)bias)[lane];
    float2 r;
    r.x = fmaxf(fmaf(d, a.x, bb.x), 0.f);
    r.y = fmaxf(fmaf(d, a.y, bb.y), 0.f);
    ((float2*)g_g2)[gw * 32 + lane] = r;
}

// ---------------- mean pool + classifier ----------------
__global__ void pool_cls_kernel(const float* __restrict__ clsw,
                                const float* __restrict__ clsb,
                                float* __restrict__ out) {
    __shared__ float sp[256];
    __shared__ float pooled[64];
    const int b = blockIdx.x, tid = threadIdx.x;
    const int c = tid & 63, q = tid >> 6;
    float s = 0.f;
    for (int n = q; n < T4; n += 4)
        s += g_g2[((size_t)b * T4 + n) * 64 + c];
    sp[tid] = s;
    __syncthreads();
    if (tid < 64)
        pooled[tid] = (sp[tid] + sp[tid + 64] + sp[tid + 128] + sp[tid + 192]) * (1.f / (float)T4);
    __syncthreads();
    if (tid < OUTC) {
        float acc = clsb[tid];
#pragma unroll
        for (int cc = 0; cc < 64; cc++) acc += pooled[cc] * clsw[cc * OUTC + tid];
        out[b * OUTC + tid] = acc;
    }
}

// ---------------- launch ----------------
extern "C" void kernel_launch(void* const* d_in, const int* in_sizes, int n_in,
                              void* d_out, int out_size) {
    const float* x       = nullptr;
    const int*   ei      = nullptr;
    const float* conv1_w = nullptr; const float* conv1_b = nullptr;
    const float* conv2_w = nullptr; const float* conv2_b = nullptr;
    const float* gcn1_w  = nullptr; const float* gcn1_b  = nullptr;
    const float* gcn2_w  = nullptr; const float* gcn2_b  = nullptr;
    const float* cls_w   = nullptr; const float* cls_b   = nullptr;

    for (int i = 0; i < n_in; i++) {
        switch (in_sizes[i]) {
            case BATCH * 16 * T_IN:   x       = (const float*)d_in[i]; break;
            case 2 * N_EDGES:         ei      = (const int*)  d_in[i]; break;
            case 16 * 16 * 5:         conv1_w = (const float*)d_in[i]; break;
            case 16:                  conv1_b = (const float*)d_in[i]; break;
            case 32 * 16 * 5:         conv2_w = (const float*)d_in[i]; break;
            case 32:                  conv2_b = (const float*)d_in[i]; break;
            case 32 * HID:            gcn1_w  = (const float*)d_in[i]; break;
            case HID * HID:           gcn2_w  = (const float*)d_in[i]; break;
            case HID * OUTC:          cls_w   = (const float*)d_in[i]; break;
            case OUTC:                cls_b   = (const float*)d_in[i]; break;
            case HID:
                if (!gcn1_b) gcn1_b = (const float*)d_in[i];
                else         gcn2_b = (const float*)d_in[i];
                break;
            default: break;
        }
    }
    if (!x || !ei || !conv1_w || !conv2_w || !gcn1_w || !gcn2_w || !cls_w) {
        x       = (const float*)d_in[0];  ei      = (const int*)  d_in[1];
        conv1_w = (const float*)d_in[2];  conv1_b = (const float*)d_in[3];
        conv2_w = (const float*)d_in[4];  conv2_b = (const float*)d_in[5];
        gcn1_w  = (const float*)d_in[6];  gcn1_b  = (const float*)d_in[7];
        gcn2_w  = (const float*)d_in[8];  gcn2_b  = (const float*)d_in[9];
        cls_w   = (const float*)d_in[10]; cls_b   = (const float*)d_in[11];
    }

    float* out = (float*)d_out;
    const int* e_row = ei;
    const int* e_col = ei + N_EDGES;

    cudaFuncSetAttribute(conv_fused_kernel,
                         cudaFuncAttributeMaxDynamicSharedMemorySize, SM_BYTES);

    // CSR build; conv_fused at launch index 3 (profiler slot)
    zero_cnt_kernel<<<N_NODES / 256, 256>>>();
    hist_kernel<<<N_EDGES / 256, 256>>>(e_col);
    scan1_kernel<<<128, 256>>>();                 // also computes g_dis
    {
        dim3 gc(T4 / 128, BATCH);
        conv_fused_kernel<<<gc, 256, SM_BYTES>>>(x, conv1_w, conv1_b, conv2_w, conv2_b);
    }
    scan2_kernel<<<1, 128>>>();
    scan3_kernel<<<N_NODES / 256, 256>>>();
    place_kernel<<<N_EDGES / 256, 256>>>(e_row, e_col);

    // GCN layer 1 aggregate, then fused (W1 -> relu -> W2 -> dis) matmuls
    gather32_kernel<<<N_NODES / 8, 256>>>();
    xw_fused_kernel<<<N_NODES / 256, 256>>>(gcn1_w, gcn1_b, gcn2_w);

    // GCN layer 2 aggregate
    gather64_kernel<<<N_NODES / 8, 256>>>(gcn2_b);

    // mean pool + classifier
    pool_cls_kernel<<<BATCH, 256>>>(cls_w, cls_b, out);
}

// round 8
// speedup vs baseline: 1.9441x; 1.0833x over previous
#include <cuda_runtime.h>
#include <cuda_bf16.h>
#include <cuda_fp16.h>

// ---------------- problem constants ----------------
#define BATCH   64
#define T_IN    8192
#define T2      4096        // after pool1
#define T4      2048        // after pool2
#define N_NODES 131072      // BATCH * T4
#define N_EDGES 2097152
#define HID     64
#define OUTC    10

typedef unsigned long long u64;

// ---------------- f32x2 packed helpers (Blackwell) ----------------
__device__ __forceinline__ u64 pk2(float lo, float hi) {
    u64 r; asm("mov.b64 %0, {%1, %2};" : "=l"(r) : "f"(lo), "f"(hi)); return r;
}
__device__ __forceinline__ void upk2(u64 v, float& lo, float& hi) {
    asm("mov.b64 {%0, %1}, %2;" : "=f"(lo), "=f"(hi) : "l"(v));
}
__device__ __forceinline__ void fma2(u64& acc, u64 a, u64 b) {
    asm("fma.rn.f32x2 %0, %1, %2, %3;" : "=l"(acc) : "l"(a), "l"(b), "l"(acc));
}

// ---------------- scratch (device globals, no allocation) ----------------
// NOTE: referenced ONLY inside device code (GB300 ATS silently reads the host
// shadow if passed as host-side kernel args).
__device__ __half2 g_feat_h[N_NODES * 16];       // conv2 out * dis, fp16, node-major
__device__ float   g_z[N_NODES * 32];            // aggregated 32-dim features (fp32)
__device__ __half2 g_y_h[N_NODES * 32];          // dis * (relu(z@W1+b1) @ W2), fp16
__device__ float   g_pool[BATCH * 64];           // per-batch channel sums
__device__ float   g_dis[N_NODES];
__device__ int     g_cnt[N_NODES];
__device__ int     g_off[N_NODES + 1];
__device__ int     g_cur[N_NODES];
__device__ int     g_srcs[N_EDGES];
__device__ int     g_bsum[128];

// ---------------- fused conv1+conv2+pools+dis-scale -> fp16 node features -----
// grid (T4/128, BATCH) x 256 threads. Weights padded to stride 6 u64 (LDS.128
// x2 + LDS.64 per quintet). 'so' staging ALIASES sx (dead after phase 1) to
// keep dynamic smem under the 3-blocks/SM threshold.
#define SX_W   528
#define SX_V   524
#define SH1_W  264
#define SH1_V  260
#define SW1_N  (8 * 16 * 6)
#define SW2_N  (16 * 16 * 6)
#define SM_FLOATS (16*SX_W + 16*SH1_W + 16 + 32)
#define SM_BYTES  (SM_FLOATS*4 + (SW1_N + SW2_N)*8)

__global__ void conv_fused_kernel(const float* __restrict__ x,
                                  const float* __restrict__ w1,
                                  const float* __restrict__ b1,
                                  const float* __restrict__ w2,
                                  const float* __restrict__ b2) {
    extern __shared__ float sm[];
    float*   sx  = sm;                       // [16][SX_W]
    float*   sh1 = sm + 16 * SX_W;           // [16][SH1_W]
    float*   sb1 = sh1 + 16 * SH1_W;         // [16]
    float*   sb2 = sb1 + 16;                 // [32]
    u64*     sw1 = (u64*)(sb2 + 32);         // [SW1_N] stride-6 padded
    u64*     sw2 = sw1 + SW1_N;              // [SW2_N]
    __half2* so  = (__half2*)sm;             // [128*17] ALIASES sx (dead in phase 2)

    const int tile = blockIdx.x, bb = blockIdx.y, tid = threadIdx.x;

    // ---- loads ----
    const int x0 = tile * 512 - 6;
    for (int i = tid; i < 16 * SX_V; i += 256) {
        int ci = i / SX_V, j = i - ci * SX_V;
        int t = x0 + j;
        sx[ci * SX_W + j] = (t >= 0 && t < T_IN) ? x[(bb * 16 + ci) * T_IN + t] : 0.f;
    }
    for (int i = tid; i < 8 * 16 * 5; i += 256) {
        int cp = i / 80, r = i - cp * 80;       // r = ci*5 + k
        int ci = r / 5, k = r - ci * 5;
        sw1[(cp * 16 + ci) * 6 + k] = pk2(w1[(2 * cp) * 80 + r], w1[(2 * cp + 1) * 80 + r]);
    }
    for (int i = tid; i < 16 * 16 * 5; i += 256) {
        int cp = i / 80, r = i - cp * 80;
        int ci = r / 5, k = r - ci * 5;
        sw2[(cp * 16 + ci) * 6 + k] = pk2(w2[(2 * cp) * 80 + r], w2[(2 * cp + 1) * 80 + r]);
    }
    if (tid < 16) sb1[tid] = b1[tid];
    else if (tid < 48) sb2[tid - 16] = b2[tid - 16];
    __syncthreads();

    // ---- phase 1: conv1 + relu + pool over the 260-wide halo tile ----
    const int q0 = tile * 256 - 2;
    for (int j = tid; j < SH1_V; j += 256) {
        const int q = q0 + j;
        if (q < 0 || q >= T2) {
#pragma unroll
            for (int co = 0; co < 16; co++) sh1[co * SH1_W + j] = 0.f;
            continue;
        }
        const int px = 2 * j;
        u64 a0[8], a1[8];
#pragma unroll
        for (int cp = 0; cp < 8; cp++) { a0[cp] = 0ull; a1[cp] = 0ull; }
#pragma unroll
        for (int ci = 0; ci < 16; ci++) {
            const float2* sxp = (const float2*)&sx[ci * SX_W + px];
            float2 v01 = sxp[0], v23 = sxp[1], v45 = sxp[2];
            u64 x0p = pk2(v01.x, v01.x), x1p = pk2(v01.y, v01.y), x2p = pk2(v23.x, v23.x);
            u64 x3p = pk2(v23.y, v23.y), x4p = pk2(v45.x, v45.x), x5p = pk2(v45.y, v45.y);
#pragma unroll
            for (int cp = 0; cp < 8; cp++) {
                const u64* wp = &sw1[(cp * 16 + ci) * 6];
                ulonglong2 wA = *(const ulonglong2*)wp;        // w0, w1
                ulonglong2 wB = *(const ulonglong2*)(wp + 2);  // w2, w3
                u64 w4 = wp[4];
                fma2(a0[cp], wA.x, x0p); fma2(a1[cp], wA.x, x1p);
                fma2(a0[cp], wA.y, x1p); fma2(a1[cp], wA.y, x2p);
                fma2(a0[cp], wB.x, x2p); fma2(a1[cp], wB.x, x3p);
                fma2(a0[cp], wB.y, x3p); fma2(a1[cp], wB.y, x4p);
                fma2(a0[cp], w4,   x4p); fma2(a1[cp], w4,   x5p);
            }
        }
#pragma unroll
        for (int cp = 0; cp < 8; cp++) {
            float e0, o0, e1, o1;
            upk2(a0[cp], e0, o0);
            upk2(a1[cp], e1, o1);
            sh1[(2 * cp) * SH1_W + j]     = fmaxf(fmaxf(e0, e1) + sb1[2 * cp], 0.f);
            sh1[(2 * cp + 1) * SH1_W + j] = fmaxf(fmaxf(o0, o1) + sb1[2 * cp + 1], 0.f);
        }
    }
    __syncthreads();   // sx dead beyond this point; so may reuse it

    // ---- phase 2: conv2 + relu + pool + dis scale, fp16 transpose write ----
    const int tp  = tid & 127;
    const int cob = tid >> 7;
    const int p0  = 2 * tp;

    u64 acc0[8], acc1[8];
#pragma unroll
    for (int q = 0; q < 8; q++) { acc0[q] = 0ull; acc1[q] = 0ull; }

#pragma unroll
    for (int ci = 0; ci < 16; ci++) {
        const float2* shp = (const float2*)&sh1[ci * SH1_W + p0];
        float2 v01 = shp[0], v23 = shp[1], v45 = shp[2];
        u64 x0p = pk2(v01.x, v01.x), x1p = pk2(v01.y, v01.y), x2p = pk2(v23.x, v23.x);
        u64 x3p = pk2(v23.y, v23.y), x4p = pk2(v45.x, v45.x), x5p = pk2(v45.y, v45.y);
#pragma unroll
        for (int q = 0; q < 8; q++) {
            const u64* wp = &sw2[((cob * 8 + q) * 16 + ci) * 6];
            ulonglong2 wA = *(const ulonglong2*)wp;
            ulonglong2 wB = *(const ulonglong2*)(wp + 2);
            u64 w4 = wp[4];
            fma2(acc0[q], wA.x, x0p); fma2(acc1[q], wA.x, x1p);
            fma2(acc0[q], wA.y, x1p); fma2(acc1[q], wA.y, x2p);
            fma2(acc0[q], wB.x, x2p); fma2(acc1[q], wB.x, x3p);
            fma2(acc0[q], wB.y, x3p); fma2(acc1[q], wB.y, x4p);
            fma2(acc0[q], w4,   x4p); fma2(acc1[q], w4,   x5p);
        }
    }

    const int node_base = bb * T4 + tile * 128;
    const float d = __ldg(&g_dis[node_base + tp]);
#pragma unroll
    for (int q = 0; q < 8; q++) {
        int cp = cob * 8 + q;
        float e0, o0, e1, o1;
        upk2(acc0[q], e0, o0);
        upk2(acc1[q], e1, o1);
        float re = fmaxf(fmaxf(e0, e1) + sb2[2 * cp], 0.f) * d;
        float ro = fmaxf(fmaxf(o0, o1) + sb2[2 * cp + 1], 0.f) * d;
        so[tp * 17 + cp] = __floats2half2_rn(re, ro);
    }
    __syncthreads();

    for (int i = tid; i < 128 * 16; i += 256) {
        int lp = i >> 4, c = i & 15;
        g_feat_h[(node_base + lp) * 16 + c] = so[lp * 17 + c];
    }
}

// ---------------- CSR build ----------------
__global__ void zero_cnt_kernel() {
    int i = blockIdx.x * blockDim.x + threadIdx.x;
    if (i < N_NODES) g_cnt[i] = 0;
    if (i < BATCH * 64) g_pool[i] = 0.f;
}

__global__ void hist_kernel(const int* __restrict__ col) {
    int e = blockIdx.x * blockDim.x + threadIdx.x;
    if (e < N_EDGES) atomicAdd(&g_cnt[col[e]], 1);
}

// scan1 also produces g_dis (counts already in registers)
__global__ void scan1_kernel() {
    __shared__ int ss[256];
    const int tid = threadIdx.x;
    const int base = blockIdx.x * 1024 + tid * 4;
    int v0 = g_cnt[base], v1 = g_cnt[base + 1], v2 = g_cnt[base + 2], v3 = g_cnt[base + 3];
    g_dis[base]     = rsqrtf((float)(v0 + 1));
    g_dis[base + 1] = rsqrtf((float)(v1 + 1));
    g_dis[base + 2] = rsqrtf((float)(v2 + 1));
    g_dis[base + 3] = rsqrtf((float)(v3 + 1));
    int tsum = v0 + v1 + v2 + v3;
    ss[tid] = tsum;
    __syncthreads();
    for (int d = 1; d < 256; d <<= 1) {
        int t = (tid >= d) ? ss[tid - d] : 0;
        __syncthreads();
        ss[tid] += t;
        __syncthreads();
    }
    int excl = ss[tid] - tsum;
    g_off[base]     = excl;
    g_off[base + 1] = excl + v0;
    g_off[base + 2] = excl + v0 + v1;
    g_off[base + 3] = excl + v0 + v1 + v2;
    if (tid == 255) g_bsum[blockIdx.x] = ss[255];
}

__global__ void scan2_kernel() {
    __shared__ int ss[128];
    const int tid = threadIdx.x;
    int v = g_bsum[tid];
    ss[tid] = v;
    __syncthreads();
    for (int d = 1; d < 128; d <<= 1) {
        int t = (tid >= d) ? ss[tid - d] : 0;
        __syncthreads();
        ss[tid] += t;
        __syncthreads();
    }
    g_bsum[tid] = ss[tid] - v;
}

__global__ void scan3_kernel() {
    int i = blockIdx.x * blockDim.x + threadIdx.x;
    if (i < N_NODES) {
        int o = g_off[i] + g_bsum[i >> 10];
        g_off[i] = o;
        g_cur[i] = o;
        if (i == 0) g_off[N_NODES] = N_EDGES;
    }
}

__global__ void place_kernel(const int* __restrict__ row, const int* __restrict__ col) {
    int e = blockIdx.x * blockDim.x + threadIdx.x;
    if (e < N_EDGES) {
        int c = col[e];
        int p = atomicAdd(&g_cur[c], 1);
        g_srcs[p] = row[e];
    }
}

// ---------------- gather32 (fp16): z[i] = dis_i * (feat~[i] + sum feat~[j]) ----
__global__ void gather32_kernel() {
    const int gw = (blockIdx.x * 256 + threadIdx.x) >> 5;
    const int lane = threadIdx.x & 31;
    const int hw = lane >> 4, c = lane & 15;
    const __half2* __restrict__ y = g_feat_h;

    float ax = 0.f, ay = 0.f;
    int p = g_off[gw];
    const int e = g_off[gw + 1];
    for (; p + 8 <= e; p += 8) {
        int j0 = __ldg(&g_srcs[p + 0 + hw]);
        int j1 = __ldg(&g_srcs[p + 2 + hw]);
        int j2 = __ldg(&g_srcs[p + 4 + hw]);
        int j3 = __ldg(&g_srcs[p + 6 + hw]);
        float2 v0 = __half22float2(__ldg(&y[j0 * 16 + c]));
        float2 v1 = __half22float2(__ldg(&y[j1 * 16 + c]));
        float2 v2 = __half22float2(__ldg(&y[j2 * 16 + c]));
        float2 v3 = __half22float2(__ldg(&y[j3 * 16 + c]));
        ax += (v0.x + v1.x) + (v2.x + v3.x);
        ay += (v0.y + v1.y) + (v2.y + v3.y);
    }
    for (; p + 2 <= e; p += 2) {
        int j = __ldg(&g_srcs[p + hw]);
        float2 v = __half22float2(__ldg(&y[j * 16 + c]));
        ax += v.x; ay += v.y;
    }
    if (p < e && hw == 0) {
        int j = __ldg(&g_srcs[p]);
        float2 v = __half22float2(__ldg(&y[j * 16 + c]));
        ax += v.x; ay += v.y;
    }
    ax += __shfl_xor_sync(0xFFFFFFFFu, ax, 16);
    ay += __shfl_xor_sync(0xFFFFFFFFu, ay, 16);
    if (lane < 16) {
        float2 self = __half22float2(__ldg(&y[gw * 16 + c]));
        const float d = g_dis[gw];
        float2 r;
        r.x = (self.x + ax) * d;
        r.y = (self.y + ay) * d;
        ((float2*)g_z)[gw * 16 + c] = r;
    }
}

// ---------------- fused GCN matmuls: y = dis * (relu(z@W1 + b1) @ W2), fp16 ----
__global__ void xw_fused_kernel(const float* __restrict__ W1,
                                const float* __restrict__ b1,
                                const float* __restrict__ W2) {
    __shared__ __align__(16) u64 sW1[32 * 32];
    __shared__ __align__(16) u64 sW2[64 * 32];
    __shared__ float sb1v[64];
    const int tid = threadIdx.x;
    for (int i = tid; i < 32 * 32; i += 256) {
        float2 wv = ((const float2*)W1)[i];
        sW1[i] = pk2(wv.x, wv.y);
    }
    for (int i = tid; i < 64 * 32; i += 256) {
        float2 wv = ((const float2*)W2)[i];
        sW2[i] = pk2(wv.x, wv.y);
    }
    if (tid < 64) sb1v[tid] = b1[tid];
    __syncthreads();

    const int n = blockIdx.x * 256 + tid;

    u64 acc1[32];
#pragma unroll
    for (int j = 0; j < 32; j++) acc1[j] = 0ull;
    const float4* fv = (const float4*)(g_z + (size_t)n * 32);
#pragma unroll
    for (int kc = 0; kc < 8; kc++) {
        float4 xv = fv[kc];
#pragma unroll
        for (int kk = 0; kk < 4; kk++) {
            float xk = (kk == 0) ? xv.x : (kk == 1) ? xv.y : (kk == 2) ? xv.z : xv.w;
            u64 x2 = pk2(xk, xk);
            const ulonglong2* wrow = (const ulonglong2*)&sW1[(kc * 4 + kk) * 32];
#pragma unroll
            for (int j = 0; j < 16; j++) {
                ulonglong2 wv = wrow[j];
                fma2(acc1[2 * j],     x2, wv.x);
                fma2(acc1[2 * j + 1], x2, wv.y);
            }
        }
    }

    u64 acc2[32];
#pragma unroll
    for (int j = 0; j < 32; j++) acc2[j] = 0ull;
#pragma unroll
    for (int j = 0; j < 32; j++) {
        float l, h;
        upk2(acc1[j], l, h);
        l = fmaxf(l + sb1v[2 * j], 0.f);
        h = fmaxf(h + sb1v[2 * j + 1], 0.f);
        u64 xl = pk2(l, l), xh = pk2(h, h);
        const ulonglong2* r0 = (const ulonglong2*)&sW2[(2 * j) * 32];
        const ulonglong2* r1 = (const ulonglong2*)&sW2[(2 * j + 1) * 32];
#pragma unroll
        for (int m = 0; m < 16; m++) {
            ulonglong2 wa = r0[m];
            fma2(acc2[2 * m],     xl, wa.x);
            fma2(acc2[2 * m + 1], xl, wa.y);
            ulonglong2 wb = r1[m];
            fma2(acc2[2 * m],     xh, wb.x);
            fma2(acc2[2 * m + 1], xh, wb.y);
        }
    }

    const float di = g_dis[n];
    __half2* o = g_y_h + (size_t)n * 32;
#pragma unroll
    for (int q = 0; q < 8; q++) {
        float l0, h0, l1, h1, l2, h2, l3, h3;
        upk2(acc2[4 * q + 0], l0, h0);
        upk2(acc2[4 * q + 1], l1, h1);
        upk2(acc2[4 * q + 2], l2, h2);
        upk2(acc2[4 * q + 3], l3, h3);
        __half2 a = __floats2half2_rn(l0 * di, h0 * di);
        __half2 b = __floats2half2_rn(l1 * di, h1 * di);
        __half2 cc = __floats2half2_rn(l2 * di, h2 * di);
        __half2 dd = __floats2half2_rn(l3 * di, h3 * di);
        uint4 pack;
        pack.x = *(unsigned*)&a;  pack.y = *(unsigned*)&b;
        pack.z = *(unsigned*)&cc; pack.w = *(unsigned*)&dd;
        ((uint4*)o)[q] = pack;
    }
}

// ---------------- gather64 + fused mean-pool partial reduction ----------------
// g2 values never hit DRAM: block-local channel sums -> atomicAdd to g_pool.
__global__ void gather64_pool_kernel(const float* __restrict__ bias) {
    __shared__ float pool[64];
    const __half2* __restrict__ y = g_y_h;
    const int tid = threadIdx.x;
    const int gw = (blockIdx.x * 256 + tid) >> 5;
    const int lane = tid & 31;
    if (tid < 64) pool[tid] = 0.f;
    __syncthreads();

    float2 a = __half22float2(__ldg(&y[gw * 32 + lane]));
    int p = g_off[gw];
    const int e = g_off[gw + 1];
    for (; p + 8 <= e; p += 8) {
        int j0 = __ldg(&g_srcs[p + 0]), j1 = __ldg(&g_srcs[p + 1]);
        int j2 = __ldg(&g_srcs[p + 2]), j3 = __ldg(&g_srcs[p + 3]);
        int j4 = __ldg(&g_srcs[p + 4]), j5 = __ldg(&g_srcs[p + 5]);
        int j6 = __ldg(&g_srcs[p + 6]), j7 = __ldg(&g_srcs[p + 7]);
        float2 v0 = __half22float2(__ldg(&y[j0 * 32 + lane]));
        float2 v1 = __half22float2(__ldg(&y[j1 * 32 + lane]));
        float2 v2 = __half22float2(__ldg(&y[j2 * 32 + lane]));
        float2 v3 = __half22float2(__ldg(&y[j3 * 32 + lane]));
        float2 v4 = __half22float2(__ldg(&y[j4 * 32 + lane]));
        float2 v5 = __half22float2(__ldg(&y[j5 * 32 + lane]));
        float2 v6 = __half22float2(__ldg(&y[j6 * 32 + lane]));
        float2 v7 = __half22float2(__ldg(&y[j7 * 32 + lane]));
        a.x += ((v0.x + v1.x) + (v2.x + v3.x)) + ((v4.x + v5.x) + (v6.x + v7.x));
        a.y += ((v0.y + v1.y) + (v2.y + v3.y)) + ((v4.y + v5.y) + (v6.y + v7.y));
    }
    for (; p < e; p++) {
        int j = __ldg(&g_srcs[p]);
        float2 v = __half22float2(__ldg(&y[j * 32 + lane]));
        a.x += v.x; a.y += v.y;
    }
    const float d = g_dis[gw];
    float2 bb = ((const float2*)bias)[lane];
    float rx = fmaxf(fmaf(d, a.x, bb.x), 0.f);
    float ry = fmaxf(fmaf(d, a.y, bb.y), 0.f);
    atomicAdd(&pool[2 * lane],     rx);
    atomicAdd(&pool[2 * lane + 1], ry);
    __syncthreads();
    if (tid < 64) {
        const int batch = gw >> 11;      // 2048 nodes per batch; 8 nodes/block aligned
        atomicAdd(&g_pool[batch * 64 + tid], pool[tid]);
    }
}

// ---------------- classifier from pooled sums ----------------
__global__ void cls_kernel(const float* __restrict__ clsw,
                           const float* __restrict__ clsb,
                           float* __restrict__ out) {
    __shared__ float sw[64 * OUTC];
    const int tid = threadIdx.x;
    if (tid < 64 * OUTC) sw[tid] = clsw[tid];
    __syncthreads();
    if (tid < BATCH * OUTC) {
        const int b = tid / OUTC, o = tid - b * OUTC;
        float acc = clsb[o];
#pragma unroll
        for (int c = 0; c < 64; c++)
            acc += g_pool[b * 64 + c] * sw[c * OUTC + o];
        out[tid] = acc * (1.f / (float)T4) + clsb[o] * (1.f - 1.f / (float)T4);
    }
}

// NOTE on cls math: out = (pool/T4) @ W + b. Implemented as
// (pool @ W) * (1/T4) + b. The line above folds it exactly:
// acc = b + pool@W; result = acc/T4 + b*(1-1/T4) = pool@W/T4 + b. OK.

// ---------------- launch ----------------
extern "C" void kernel_launch(void* const* d_in, const int* in_sizes, int n_in,
                              void* d_out, int out_size) {
    const float* x       = nullptr;
    const int*   ei      = nullptr;
    const float* conv1_w = nullptr; const float* conv1_b = nullptr;
    const float* conv2_w = nullptr; const float* conv2_b = nullptr;
    const float* gcn1_w  = nullptr; const float* gcn1_b  = nullptr;
    const float* gcn2_w  = nullptr; const float* gcn2_b  = nullptr;
    const float* cls_w   = nullptr; const float* cls_b   = nullptr;

    for (int i = 0; i < n_in; i++) {
        switch (in_sizes[i]) {
            case BATCH * 16 * T_IN:   x       = (const float*)d_in[i]; break;
            case 2 * N_EDGES:         ei      = (const int*)  d_in[i]; break;
            case 16 * 16 * 5:         conv1_w = (const float*)d_in[i]; break;
            case 16:                  conv1_b = (const float*)d_in[i]; break;
            case 32 * 16 * 5:         conv2_w = (const float*)d_in[i]; break;
            case 32:                  conv2_b = (const float*)d_in[i]; break;
            case 32 * HID:            gcn1_w  = (const float*)d_in[i]; break;
            case HID * HID:           gcn2_w  = (const float*)d_in[i]; break;
            case HID * OUTC:          cls_w   = (const float*)d_in[i]; break;
            case OUTC:                cls_b   = (const float*)d_in[i]; break;
            case HID:
                if (!gcn1_b) gcn1_b = (const float*)d_in[i];
                else         gcn2_b = (const float*)d_in[i];
                break;
            default: break;
        }
    }
    if (!x || !ei || !conv1_w || !conv2_w || !gcn1_w || !gcn2_w || !cls_w) {
        x       = (const float*)d_in[0];  ei      = (const int*)  d_in[1];
        conv1_w = (const float*)d_in[2];  conv1_b = (const float*)d_in[3];
        conv2_w = (const float*)d_in[4];  conv2_b = (const float*)d_in[5];
        gcn1_w  = (const float*)d_in[6];  gcn1_b  = (const float*)d_in[7];
        gcn2_w  = (const float*)d_in[8];  gcn2_b  = (const float*)d_in[9];
        cls_w   = (const float*)d_in[10]; cls_b   = (const float*)d_in[11];
    }

    float* out = (float*)d_out;
    const int* e_row = ei;
    const int* e_col = ei + N_EDGES;

    cudaFuncSetAttribute(conv_fused_kernel,
                         cudaFuncAttributeMaxDynamicSharedMemorySize, SM_BYTES);

    // CSR build; conv_fused at launch index 3 (profiler slot)
    zero_cnt_kernel<<<N_NODES / 256, 256>>>();
    hist_kernel<<<N_EDGES / 256, 256>>>(e_col);
    scan1_kernel<<<128, 256>>>();                 // also computes g_dis
    {
        dim3 gc(T4 / 128, BATCH);
        conv_fused_kernel<<<gc, 256, SM_BYTES>>>(x, conv1_w, conv1_b, conv2_w, conv2_b);
    }
    scan2_kernel<<<1, 128>>>();
    scan3_kernel<<<N_NODES / 256, 256>>>();
    place_kernel<<<N_EDGES / 256, 256>>>(e_row, e_col);

    // GCN layer 1 aggregate, then fused (W1 -> relu -> W2 -> dis) matmuls
    gather32_kernel<<<N_NODES / 8, 256>>>();
    xw_fused_kernel<<<N_NODES / 256, 256>>>(gcn1_w, gcn1_b, gcn2_w);

    // GCN layer 2 aggregate + fused mean-pool partials
    gather64_pool_kernel<<<N_NODES / 8, 256>>>(gcn2_b);

    // classifier
    cls_kernel<<<1, 640>>>(cls_w, cls_b, out);
}